// round 6
// baseline (speedup 1.0000x reference)
#include <cuda_runtime.h>

// ---------------------------------------------------------------------------
// GCNModelVAE forward on GB300 (fp32, f32x2 packed-FMA SIMT GEMMs)
//   support = x @ W_hidden                    [8192,512]@[512,256]
//   hidden  = relu(adj @ support)             [8192,8192]@[8192,256]  (split-K 2)
//   s       = hidden @ [W_mean | W_logstd]    [8192,256]@[256,128]
//   zcat    = adj @ s                         [8192,8192]@[8192,128]  (split-K 4)
//   z_mean = zcat[:, :64]; z_log_std = zcat[:, 64:]
//   recon   = z_mean @ z_mean.T               symmetric, upper CTAs only
// Output layout: [recon (8192*8192) | z_mean (8192*64) | z_log_std (8192*64)]
// ---------------------------------------------------------------------------

#define NN   8192
#define DIN  512
#define DHID 256
#define DZ   64
#define DCAT 128

typedef unsigned long long u64;

// ---- scratch (no allocations allowed: one big __device__ array) ----
#define OFF_SUPPORT 0                              // NN*DHID = 2,097,152
#define OFF_HIDDEN  (2*1024*1024 + 49152)          // 2,146,304 (keep 16B aligned)
#define OFF_PART    (2*OFF_HIDDEN)                 // plenty of headroom below
// simpler explicit offsets:
#undef OFF_HIDDEN
#undef OFF_PART
#define SZ_SUPPORT (NN*DHID)          // 2,097,152
#define SZ_HIDDEN  (NN*DHID)          // 2,097,152
#define SZ_PART    (2*NN*DHID)        // 4,194,304  (reused: 2x[NN*DHID] or 4x[NN*DCAT])
#define SZ_WCAT    (DHID*DCAT)        // 32,768
#define SZ_S       (NN*DCAT)          // 1,048,576
#define SZ_ZCAT    (NN*DCAT)          // 1,048,576
#define OFF_SUPPORT 0
#define OFF_HIDDEN  (OFF_SUPPORT + SZ_SUPPORT)
#define OFF_PART    (OFF_HIDDEN  + SZ_HIDDEN)
#define OFF_WCAT    (OFF_PART    + SZ_PART)
#define OFF_S       (OFF_WCAT    + SZ_WCAT)
#define OFF_ZCAT    (OFF_S       + SZ_S)
#define SZ_TOTAL    (OFF_ZCAT    + SZ_ZCAT)

__device__ __align__(16) float g_scratch[SZ_TOTAL];

// ---- f32x2 helpers (Blackwell packed fp32: 2 FMAs per instruction) ----
__device__ __forceinline__ void ffma2(u64& d, u64 a, u64 b) {
    asm("fma.rn.f32x2 %0, %1, %2, %0;" : "+l"(d) : "l"(a), "l"(b));
}
__device__ __forceinline__ u64 pack2(float lo, float hi) {
    u64 r; asm("mov.b64 %0, {%1, %2};" : "=l"(r) : "f"(lo), "f"(hi)); return r;
}
__device__ __forceinline__ float2 unpack2(u64 v) {
    float2 r; asm("mov.b64 {%0, %1}, %2;" : "=f"(r.x), "=f"(r.y) : "l"(v)); return r;
}

// ---- shared inner micro-kernel: 8 k-steps, 8x8 per thread, f32x2 ----
__device__ __forceinline__ void mm_inner(const float (*As)[128], const float (*Bs)[128],
                                         u64 acc[8][4], int tm, int tn) {
#pragma unroll
    for (int k = 0; k < 8; k++) {
        float4 a0 = *(const float4*)&As[k][tm * 8];
        float4 a1 = *(const float4*)&As[k][tm * 8 + 4];
        float4 b0 = *(const float4*)&Bs[k][tn * 8];
        float4 b1 = *(const float4*)&Bs[k][tn * 8 + 4];
        u64 bp0 = pack2(b0.x, b0.y);
        u64 bp1 = pack2(b0.z, b0.w);
        u64 bp2 = pack2(b1.x, b1.y);
        u64 bp3 = pack2(b1.z, b1.w);
        float a_s[8] = {a0.x, a0.y, a0.z, a0.w, a1.x, a1.y, a1.z, a1.w};
#pragma unroll
        for (int i = 0; i < 8; i++) {
            u64 ai = pack2(a_s[i], a_s[i]);
            ffma2(acc[i][0], ai, bp0);
            ffma2(acc[i][1], ai, bp1);
            ffma2(acc[i][2], ai, bp2);
            ffma2(acc[i][3], ai, bp3);
        }
    }
}

// ---------------------------------------------------------------------------
// Generic GEMM: C[M,N] (+= over split-K slices) = A[M,K] @ B[K,N], row-major.
// BM=BN=128, BK=8, 256 threads, 8x8 micro-tile. blockIdx.z = split-K slice;
// slice z writes its partial into C + z*M*N. Requires M%128==0, N%128==0,
// kChunk%8==0, K == gridDim.z*kChunk.
// ---------------------------------------------------------------------------
__global__ __launch_bounds__(256, 2)
void gemm128(const float* __restrict__ A, const float* __restrict__ B,
             float* __restrict__ C, int M, int N, int K, int kChunk) {
    __shared__ float As[8][128];
    __shared__ float Bs[8][128];

    const int tid = threadIdx.x;
    const int tm = tid >> 4;          // 0..15
    const int tn = tid & 15;          // 0..15
    const int m0 = blockIdx.y * 128;
    const int n0 = blockIdx.x * 128;
    const int kBegin = blockIdx.z * kChunk;
    const int kEnd = kBegin + kChunk;
    float* Cout = C + (size_t)blockIdx.z * (size_t)M * (size_t)N;

    u64 acc[8][4];
#pragma unroll
    for (int i = 0; i < 8; i++)
#pragma unroll
        for (int j = 0; j < 4; j++) acc[i][j] = 0ull;

    // A tile loader: 128 rows x 8 cols, transpose-scatter into As[k][m]
    const int arow = tid >> 1;            // 0..127
    const int akb = (tid & 1) * 4;        // 0 or 4
    // B tile loader: 8 rows x 128 cols, direct into Bs[k][n]
    const int bkr = tid >> 5;             // 0..7
    const int bc4 = (tid & 31) * 4;       // 0..124

    const float* Aptr = A + (size_t)(m0 + arow) * (size_t)K + akb;
    const float* Bptr = B + (size_t)bkr * (size_t)N + n0 + bc4;

    float4 av = *(const float4*)(Aptr + kBegin);
    float4 bv = *(const float4*)(Bptr + (size_t)kBegin * (size_t)N);

    for (int k0 = kBegin; k0 < kEnd; k0 += 8) {
        As[akb + 0][arow] = av.x;
        As[akb + 1][arow] = av.y;
        As[akb + 2][arow] = av.z;
        As[akb + 3][arow] = av.w;
        *(float4*)&Bs[bkr][bc4] = bv;
        __syncthreads();

        const int k1 = k0 + 8;
        if (k1 < kEnd) {
            av = *(const float4*)(Aptr + k1);
            bv = *(const float4*)(Bptr + (size_t)k1 * (size_t)N);
        }

        mm_inner(As, Bs, acc, tm, tn);
        __syncthreads();
    }

    // epilogue
    float* Crow = Cout + (size_t)(m0 + tm * 8) * (size_t)N + n0 + tn * 8;
#pragma unroll
    for (int i = 0; i < 8; i++) {
        float2 v0 = unpack2(acc[i][0]);
        float2 v1 = unpack2(acc[i][1]);
        float2 v2 = unpack2(acc[i][2]);
        float2 v3 = unpack2(acc[i][3]);
        float4 o0 = make_float4(v0.x, v0.y, v1.x, v1.y);
        float4 o1 = make_float4(v2.x, v2.y, v3.x, v3.y);
        *(float4*)(Crow + (size_t)i * (size_t)N) = o0;
        *(float4*)(Crow + (size_t)i * (size_t)N + 4) = o1;
    }
}

// ---------------------------------------------------------------------------
// Symmetric rank-K: recon = Z @ Z^T, Z:[NN, DZ]. Only bj>=bi CTAs compute;
// off-diagonal tiles are mirrored into the lower triangle.
// ---------------------------------------------------------------------------
__global__ __launch_bounds__(256, 2)
void recon_syrk(const float* __restrict__ Z, float* __restrict__ C) {
    const int bi = blockIdx.y, bj = blockIdx.x;
    if (bj < bi) return;

    __shared__ float As[8][128];
    __shared__ float Bs[8][128];

    const int tid = threadIdx.x;
    const int tm = tid >> 4;
    const int tn = tid & 15;
    const int m0 = bi * 128;
    const int n0 = bj * 128;
    const int row = tid >> 1;
    const int kb = (tid & 1) * 4;

    u64 acc[8][4];
#pragma unroll
    for (int i = 0; i < 8; i++)
#pragma unroll
        for (int j = 0; j < 4; j++) acc[i][j] = 0ull;

    const float* Ap = Z + (size_t)(m0 + row) * DZ + kb;
    const float* Bp = Z + (size_t)(n0 + row) * DZ + kb;
    float4 av = *(const float4*)Ap;
    float4 bv = *(const float4*)Bp;

    for (int k0 = 0; k0 < DZ; k0 += 8) {
        As[kb + 0][row] = av.x; As[kb + 1][row] = av.y;
        As[kb + 2][row] = av.z; As[kb + 3][row] = av.w;
        Bs[kb + 0][row] = bv.x; Bs[kb + 1][row] = bv.y;
        Bs[kb + 2][row] = bv.z; Bs[kb + 3][row] = bv.w;
        __syncthreads();

        const int k1 = k0 + 8;
        if (k1 < DZ) {
            av = *(const float4*)(Ap + k1);
            bv = *(const float4*)(Bp + k1);
        }

        mm_inner(As, Bs, acc, tm, tn);
        __syncthreads();
    }

    const size_t ldc = NN;
#pragma unroll
    for (int i = 0; i < 8; i++) {
        float v[8];
        float2 t;
        t = unpack2(acc[i][0]); v[0] = t.x; v[1] = t.y;
        t = unpack2(acc[i][1]); v[2] = t.x; v[3] = t.y;
        t = unpack2(acc[i][2]); v[4] = t.x; v[5] = t.y;
        t = unpack2(acc[i][3]); v[6] = t.x; v[7] = t.y;
        const size_t r = (size_t)(m0 + tm * 8 + i);
        const size_t c = (size_t)(n0 + tn * 8);
        float4 o0 = make_float4(v[0], v[1], v[2], v[3]);
        float4 o1 = make_float4(v[4], v[5], v[6], v[7]);
        *(float4*)&C[r * ldc + c] = o0;
        *(float4*)&C[r * ldc + c + 4] = o1;
        if (bi != bj) {
#pragma unroll
            for (int j = 0; j < 8; j++) C[(c + j) * ldc + r] = v[j];
        }
    }
}

// ---- small helper kernels ----
__global__ void pack_w(const float* __restrict__ Wm, const float* __restrict__ Wl,
                       float* __restrict__ Wcat) {
    int i = blockIdx.x * blockDim.x + threadIdx.x;   // DHID*DCAT = 32768
    if (i >= DHID * DCAT) return;
    int r = i >> 7, c = i & 127;
    Wcat[i] = (c < DZ) ? Wm[r * DZ + c] : Wl[r * DZ + (c - DZ)];
}

__global__ void reduce2_relu(const float* __restrict__ p0, const float* __restrict__ p1,
                             float* __restrict__ out, int n4) {
    int i = blockIdx.x * blockDim.x + threadIdx.x;
    if (i >= n4) return;
    float4 a = ((const float4*)p0)[i];
    float4 b = ((const float4*)p1)[i];
    float4 r;
    r.x = fmaxf(a.x + b.x, 0.f);
    r.y = fmaxf(a.y + b.y, 0.f);
    r.z = fmaxf(a.z + b.z, 0.f);
    r.w = fmaxf(a.w + b.w, 0.f);
    ((float4*)out)[i] = r;
}

__global__ void reduce4(const float* __restrict__ p, float* __restrict__ out,
                        int n4, size_t strideElems) {
    int i = blockIdx.x * blockDim.x + threadIdx.x;
    if (i >= n4) return;
    const float4* p0 = (const float4*)p;
    const float4* p1 = (const float4*)(p + strideElems);
    const float4* p2 = (const float4*)(p + 2 * strideElems);
    const float4* p3 = (const float4*)(p + 3 * strideElems);
    float4 a = p0[i], b = p1[i], c = p2[i], d = p3[i];
    float4 r;
    r.x = a.x + b.x + c.x + d.x;
    r.y = a.y + b.y + c.y + d.y;
    r.z = a.z + b.z + c.z + d.z;
    r.w = a.w + b.w + c.w + d.w;
    ((float4*)out)[i] = r;
}

__global__ void split_z(const float* __restrict__ zcat, float* __restrict__ zm,
                        float* __restrict__ zl) {
    int i = blockIdx.x * blockDim.x + threadIdx.x;   // over NN*DCAT/4 float4s
    if (i >= NN * DCAT / 4) return;
    int row = i >> 5;          // DCAT/4 = 32 float4 per row
    int c4 = i & 31;
    float4 v = ((const float4*)zcat)[i];
    if (c4 < 16) ((float4*)zm)[(size_t)row * 16 + c4] = v;
    else         ((float4*)zl)[(size_t)row * 16 + (c4 - 16)] = v;
}

// ---------------------------------------------------------------------------
extern "C" void kernel_launch(void* const* d_in, const int* in_sizes, int n_in,
                              void* d_out, int out_size) {
    // Identify inputs by element count (robust to ordering except Wm/Wl, which
    // keep dict order): x 4,194,304 | adj 67,108,864 | W_hidden 131,072 |
    // W_mean 16,384 | W_logstd 16,384
    const float* x = nullptr;
    const float* adj = nullptr;
    const float* Wh = nullptr;
    const float* Wsmall[2] = {nullptr, nullptr};
    int nsmall = 0;
    for (int i = 0; i < n_in; i++) {
        const float* p = (const float*)d_in[i];
        switch (in_sizes[i]) {
            case NN * DIN:   x = p; break;
            case NN * NN:    adj = p; break;
            case DIN * DHID: Wh = p; break;
            case DHID * DZ:  if (nsmall < 2) Wsmall[nsmall++] = p; break;
            default: break;
        }
    }
    const float* Wm = Wsmall[0];
    const float* Wl = Wsmall[1];

    float* out = (float*)d_out;
    float* recon = out;
    float* zm = out + (size_t)NN * (size_t)NN;
    float* zl = zm + (size_t)NN * (size_t)DZ;

    float* ws = nullptr;
    cudaGetSymbolAddress((void**)&ws, g_scratch);
    float* support = ws + OFF_SUPPORT;
    float* hidden  = ws + OFF_HIDDEN;
    float* part    = ws + OFF_PART;
    float* wcat    = ws + OFF_WCAT;
    float* sbuf    = ws + OFF_S;
    float* zcat    = ws + OFF_ZCAT;

    // 1. Wcat = [W_mean | W_logstd]  (independent of the GCN chain)
    pack_w<<<(DHID * DCAT + 255) / 256, 256>>>(Wm, Wl, wcat);

    // 2. support = x @ W_hidden   [8192,512]@[512,256]
    gemm128<<<dim3(DHID / 128, NN / 128, 1), 256>>>(x, Wh, support, NN, DHID, DIN, DIN);

    // 3. hidden = relu(adj @ support)   split-K 2
    gemm128<<<dim3(DHID / 128, NN / 128, 2), 256>>>(adj, support, part, NN, DHID, NN, NN / 2);
    reduce2_relu<<<(NN * DHID / 4 + 255) / 256, 256>>>(part, part + (size_t)NN * DHID,
                                                       hidden, NN * DHID / 4);

    // 4. s = hidden @ Wcat   [8192,256]@[256,128]
    gemm128<<<dim3(DCAT / 128, NN / 128, 1), 256>>>(hidden, wcat, sbuf, NN, DCAT, DHID, DHID);

    // 5. zcat = adj @ s   split-K 4
    gemm128<<<dim3(DCAT / 128, NN / 128, 4), 256>>>(adj, sbuf, part, NN, DCAT, NN, NN / 4);
    reduce4<<<(NN * DCAT / 4 + 255) / 256, 256>>>(part, zcat, NN * DCAT / 4,
                                                  (size_t)NN * DCAT);

    // 6. split zcat -> z_mean, z_log_std (into output buffer)
    split_z<<<(NN * DCAT / 4 + 255) / 256, 256>>>(zcat, zm, zl);

    // 7. recon = z_mean @ z_mean^T (symmetric)
    recon_syrk<<<dim3(NN / 128, NN / 128), 256>>>(zm, recon);
}

// round 8
// speedup vs baseline: 2.2659x; 2.2659x over previous
#include <cuda_runtime.h>
#include <cuda_bf16.h>
#include <cstdint>

// ---------------------------------------------------------------------------
// GCNModelVAE forward — bf16 mma.sync GEMMs with 3-term error compensation.
// (tcgen05 is unavailable: harness ptxas targets plain sm_103, no 'a' features)
//   support = x @ Wh                  [8192,512]@[512,256]
//   hidden  = relu(adj @ support)     [8192,8192]@[8192,256]  split-K 2
//   s       = hidden @ [Wm|Wl]        [8192,256]@[256,128]
//   zcat    = adj @ s                 [8192,8192]@[8192,128]  split-K 2
//   recon   = z_mean @ z_mean^T       [8192,64] rank-k
// Output: [recon | z_mean | z_log_std]
//
// Compensation: a = ah + al (bf16 hi + bf16 residual);
//   C = Ah*Bl + Al*Bh + Ah*Bh   (Al*Bl ~2^-18 dropped) -> ~1e-5 per GEMM.
// ---------------------------------------------------------------------------

#define NN   8192
#define DIN  512
#define DHID 256
#define DZ   64
#define DCAT 128

// ---- scratch (allocation-free) ----
#define OFF_SUPPORT 0
#define OFF_SUPT    (OFF_SUPPORT + NN*DHID)
#define OFF_HIDDEN  (OFF_SUPT    + NN*DHID)
#define OFF_PART    (OFF_HIDDEN  + NN*DHID)
#define OFF_S       (OFF_PART    + 2*NN*DHID)
#define OFF_ST      (OFF_S       + NN*DCAT)
#define OFF_WHT     (OFF_ST      + NN*DCAT)
#define OFF_WCT     (OFF_WHT     + DIN*DHID)
#define SZ_TOTAL    (OFF_WCT     + DHID*DCAT)

__device__ __align__(16) float g_scratch[SZ_TOTAL];

// ---------------------------------------------------------------------------
// helpers
// ---------------------------------------------------------------------------
__device__ __forceinline__ uint32_t smem_u32(const void* p) {
    uint32_t a;
    asm("{ .reg .u64 t; cvta.to.shared.u64 t, %1; cvt.u32.u64 %0, t; }"
        : "=r"(a) : "l"(p));
    return a;
}

// pack (lo, hi) floats -> bf16x2 (lo in low 16 bits), round-to-nearest
__device__ __forceinline__ uint32_t pack_bf2(float lo, float hi) {
    uint32_t r;
    asm("cvt.rn.bf16x2.f32 %0, %1, %2;" : "=r"(r) : "f"(hi), "f"(lo));
    return r;
}

__device__ __forceinline__ float bf_round(float v) {
    return __bfloat162float(__float2bfloat16(v));
}

__device__ __forceinline__ void ldm_x4(uint32_t* r, uint32_t addr) {
    asm volatile("ldmatrix.sync.aligned.m8n8.x4.shared.b16 {%0,%1,%2,%3}, [%4];"
                 : "=r"(r[0]), "=r"(r[1]), "=r"(r[2]), "=r"(r[3]) : "r"(addr));
}

__device__ __forceinline__ void mma_bf16(float* c, const uint32_t* a, const uint32_t* b) {
    asm volatile(
        "mma.sync.aligned.m16n8k16.row.col.f32.bf16.bf16.f32 "
        "{%0,%1,%2,%3}, {%4,%5,%6,%7}, {%8,%9}, {%0,%1,%2,%3};"
        : "+f"(c[0]), "+f"(c[1]), "+f"(c[2]), "+f"(c[3])
        : "r"(a[0]), "r"(a[1]), "r"(a[2]), "r"(a[3]), "r"(b[0]), "r"(b[1]));
}

// ---------------------------------------------------------------------------
// bf16x3 GEMM: C[M,N] (split-K slice z at C + z*M*N) = A[M,K] @ BT[N,K]^T.
// BM=BN=128, BK=32 fp32. 256 threads, warp grid 4(m) x 2(n), warp tile 32x64.
// Smem: 4 bf16 tiles (Ah, Al, Bl, Bh), 128 rows x 64B data, 80B pitch
// (20r mod 32 -> conflict-free ldmatrix). grid=(N/128, M/128, K/kChunk).
// ---------------------------------------------------------------------------
#define PITCH   80
#define SEGSZ   (128 * PITCH)      // 10240
#define SEG_AH  0
#define SEG_AL  (1 * SEGSZ)
#define SEG_BL  (2 * SEGSZ)
#define SEG_BH  (3 * SEGSZ)

__global__ void __launch_bounds__(256)
bf16x3_gemm(const float* __restrict__ A, const float* __restrict__ BT,
            float* __restrict__ C, int M, int N, int K, int kChunk)
{
    __shared__ __align__(16) char sm[4 * SEGSZ];
    const uint32_t smb = smem_u32(sm);

    const int tid = threadIdx.x;
    const int wid = tid >> 5;
    const int lane = tid & 31;
    const int warp_m = wid & 3;        // 4 warps over M (32 rows each)
    const int warp_n = wid >> 2;       // 2 warps over N (64 cols each)

    const int m0 = blockIdx.y * 128;
    const int n0 = blockIdx.x * 128;
    const int kBeg = blockIdx.z * kChunk;
    const int nkt = kChunk >> 5;
    float* Cout = C + (size_t)blockIdx.z * (size_t)M * (size_t)N;

    float acc[2][8][4];
#pragma unroll
    for (int mt = 0; mt < 2; mt++)
#pragma unroll
        for (int nf = 0; nf < 8; nf++)
#pragma unroll
            for (int e = 0; e < 4; e++) acc[mt][nf][e] = 0.f;

    // tile loaders: thread -> (row = lr + 32i, k-float4 = c4)
    const int lr = tid >> 3;
    const int c4 = tid & 7;
    const float* Ab = A + (size_t)(m0 + lr) * (size_t)K + c4 * 4;
    const float* Bb = BT + (size_t)(n0 + lr) * (size_t)K + c4 * 4;

    float4 ra[4], rb[4];
#pragma unroll
    for (int i = 0; i < 4; i++) {
        ra[i] = *(const float4*)(Ab + (size_t)(i * 32) * (size_t)K + kBeg);
        rb[i] = *(const float4*)(Bb + (size_t)(i * 32) * (size_t)K + kBeg);
    }

    // precomputed ldmatrix address components
    const uint32_t a_row = (uint32_t)(warp_m * 32 + (lane & 15));
    const uint32_t a_off = a_row * PITCH + ((uint32_t)(lane >> 4) << 4);
    const uint32_t b_row = (uint32_t)(warp_n * 64 + (lane & 7) + ((lane >> 4) << 3));
    const uint32_t b_off = b_row * PITCH + (((uint32_t)(lane >> 3) & 1) << 4);

    for (int kt = 0; kt < nkt; kt++) {
        // ---- convert + store tile to smem ----
#pragma unroll
        for (int i = 0; i < 4; i++) {
            const uint32_t off = (uint32_t)((lr + 32 * i) * PITCH + c4 * 8);
            float4 v = ra[i];
            float h0 = bf_round(v.x), h1 = bf_round(v.y);
            float h2 = bf_round(v.z), h3 = bf_round(v.w);
            uint2 hp = make_uint2(pack_bf2(v.x, v.y), pack_bf2(v.z, v.w));
            uint2 lp = make_uint2(pack_bf2(v.x - h0, v.y - h1),
                                  pack_bf2(v.z - h2, v.w - h3));
            *(uint2*)(sm + SEG_AH + off) = hp;
            *(uint2*)(sm + SEG_AL + off) = lp;
            v = rb[i];
            h0 = bf_round(v.x); h1 = bf_round(v.y);
            h2 = bf_round(v.z); h3 = bf_round(v.w);
            hp = make_uint2(pack_bf2(v.x, v.y), pack_bf2(v.z, v.w));
            lp = make_uint2(pack_bf2(v.x - h0, v.y - h1),
                            pack_bf2(v.z - h2, v.w - h3));
            *(uint2*)(sm + SEG_BH + off) = hp;
            *(uint2*)(sm + SEG_BL + off) = lp;
        }
        __syncthreads();

        // ---- prefetch next tile (overlaps mma) ----
        if (kt + 1 < nkt) {
            const int k0 = kBeg + ((kt + 1) << 5);
#pragma unroll
            for (int i = 0; i < 4; i++) {
                ra[i] = *(const float4*)(Ab + (size_t)(i * 32) * (size_t)K + k0);
                rb[i] = *(const float4*)(Bb + (size_t)(i * 32) * (size_t)K + k0);
            }
        }

        // ---- compute: 2 k16 steps x 3 compensation passes ----
#pragma unroll
        for (int kk = 0; kk < 2; kk++) {
            const uint32_t kb = (uint32_t)(kk * 32);
            uint32_t Ah[2][4], Al[2][4];
#pragma unroll
            for (int mt = 0; mt < 2; mt++) {
                const uint32_t base = smb + a_off + (uint32_t)(mt * 16 * PITCH) + kb;
                ldm_x4(Ah[mt], base + SEG_AH);
                ldm_x4(Al[mt], base + SEG_AL);
            }
            uint32_t B[8][2];
            // pass 0: Ah * Bl
#pragma unroll
            for (int nf2 = 0; nf2 < 4; nf2++) {
                uint32_t t[4];
                ldm_x4(t, smb + SEG_BL + b_off + (uint32_t)(nf2 * 16 * PITCH) + kb);
                B[2 * nf2][0] = t[0]; B[2 * nf2][1] = t[1];
                B[2 * nf2 + 1][0] = t[2]; B[2 * nf2 + 1][1] = t[3];
            }
#pragma unroll
            for (int mt = 0; mt < 2; mt++)
#pragma unroll
                for (int nf = 0; nf < 8; nf++)
                    mma_bf16(acc[mt][nf], Ah[mt], B[nf]);
            // passes 1+2: Al * Bh, Ah * Bh
#pragma unroll
            for (int nf2 = 0; nf2 < 4; nf2++) {
                uint32_t t[4];
                ldm_x4(t, smb + SEG_BH + b_off + (uint32_t)(nf2 * 16 * PITCH) + kb);
                B[2 * nf2][0] = t[0]; B[2 * nf2][1] = t[1];
                B[2 * nf2 + 1][0] = t[2]; B[2 * nf2 + 1][1] = t[3];
            }
#pragma unroll
            for (int mt = 0; mt < 2; mt++)
#pragma unroll
                for (int nf = 0; nf < 8; nf++) {
                    mma_bf16(acc[mt][nf], Al[mt], B[nf]);
                    mma_bf16(acc[mt][nf], Ah[mt], B[nf]);
                }
        }
        __syncthreads();
    }

    // ---- epilogue ----
    const int erow = m0 + warp_m * 32 + (lane >> 2);
    const int ecol = n0 + warp_n * 64 + 2 * (lane & 3);
#pragma unroll
    for (int mt = 0; mt < 2; mt++) {
#pragma unroll
        for (int nf = 0; nf < 8; nf++) {
            float* p0 = Cout + (size_t)(erow + mt * 16) * (size_t)N + ecol + nf * 8;
            float* p1 = p0 + (size_t)8 * (size_t)N;
            *(float2*)p0 = make_float2(acc[mt][nf][0], acc[mt][nf][1]);
            *(float2*)p1 = make_float2(acc[mt][nf][2], acc[mt][nf][3]);
        }
    }
}

// ---------------------------------------------------------------------------
// helpers: transpose, pack, reduces
// ---------------------------------------------------------------------------
__global__ void transpose_k(const float* __restrict__ in, float* __restrict__ out,
                            int R, int C) {
    __shared__ float t[32][33];
    const int c0 = blockIdx.x * 32, r0 = blockIdx.y * 32;
    const int tx = threadIdx.x, ty = threadIdx.y;
#pragma unroll
    for (int j = 0; j < 4; j++)
        t[ty + j * 8][tx] = in[(size_t)(r0 + ty + j * 8) * (size_t)C + c0 + tx];
    __syncthreads();
#pragma unroll
    for (int j = 0; j < 4; j++)
        out[(size_t)(c0 + ty + j * 8) * (size_t)R + r0 + tx] = t[tx][ty + j * 8];
}

// WcT[c][r] = c<64 ? Wm[r][c] : Wl[r][c-64];  WcT is [128,256]
__global__ void pack_wct(const float* __restrict__ Wm, const float* __restrict__ Wl,
                         float* __restrict__ WcT) {
    int i = blockIdx.x * blockDim.x + threadIdx.x;    // 128*256
    if (i >= DCAT * DHID) return;
    int c = i >> 8, r = i & 255;
    WcT[i] = (c < DZ) ? Wm[r * DZ + c] : Wl[r * DZ + (c - DZ)];
}

__global__ void reduce2_relu(const float* __restrict__ p0, const float* __restrict__ p1,
                             float* __restrict__ out, int n4) {
    int i = blockIdx.x * blockDim.x + threadIdx.x;
    if (i >= n4) return;
    float4 a = ((const float4*)p0)[i];
    float4 b = ((const float4*)p1)[i];
    float4 r;
    r.x = fmaxf(a.x + b.x, 0.f);
    r.y = fmaxf(a.y + b.y, 0.f);
    r.z = fmaxf(a.z + b.z, 0.f);
    r.w = fmaxf(a.w + b.w, 0.f);
    ((float4*)out)[i] = r;
}

// zcat = p0+p1; split cols [0,64)->zm, [64,128)->zl
__global__ void reduce2_split(const float* __restrict__ p0, const float* __restrict__ p1,
                              float* __restrict__ zm, float* __restrict__ zl) {
    int i = blockIdx.x * blockDim.x + threadIdx.x;    // NN*DCAT/4
    if (i >= NN * DCAT / 4) return;
    int row = i >> 5, c4 = i & 31;
    float4 a = ((const float4*)p0)[i];
    float4 b = ((const float4*)p1)[i];
    float4 r = make_float4(a.x + b.x, a.y + b.y, a.z + b.z, a.w + b.w);
    if (c4 < 16) ((float4*)zm)[(size_t)row * 16 + c4] = r;
    else         ((float4*)zl)[(size_t)row * 16 + (c4 - 16)] = r;
}

// ---------------------------------------------------------------------------
extern "C" void kernel_launch(void* const* d_in, const int* in_sizes, int n_in,
                              void* d_out, int out_size) {
    const float* x = nullptr;
    const float* adj = nullptr;
    const float* Wh = nullptr;
    const float* Wsmall[2] = {nullptr, nullptr};
    int nsmall = 0;
    for (int i = 0; i < n_in; i++) {
        const float* p = (const float*)d_in[i];
        switch (in_sizes[i]) {
            case NN * DIN:   x = p; break;
            case NN * NN:    adj = p; break;
            case DIN * DHID: Wh = p; break;
            case DHID * DZ:  if (nsmall < 2) Wsmall[nsmall++] = p; break;
            default: break;
        }
    }
    const float* Wm = Wsmall[0];
    const float* Wl = Wsmall[1];

    float* out = (float*)d_out;
    float* recon = out;
    float* zm = out + (size_t)NN * (size_t)NN;
    float* zl = zm + (size_t)NN * (size_t)DZ;

    float* ws = nullptr;
    cudaGetSymbolAddress((void**)&ws, g_scratch);
    float* support = ws + OFF_SUPPORT;
    float* supT    = ws + OFF_SUPT;
    float* hidden  = ws + OFF_HIDDEN;
    float* part    = ws + OFF_PART;
    float* sbuf    = ws + OFF_S;
    float* sT      = ws + OFF_ST;
    float* WhT     = ws + OFF_WHT;
    float* WcT     = ws + OFF_WCT;

    // weights -> K-major
    transpose_k<<<dim3(DHID / 32, DIN / 32), dim3(32, 8)>>>(Wh, WhT, DIN, DHID);
    pack_wct<<<(DCAT * DHID + 255) / 256, 256>>>(Wm, Wl, WcT);

    // support = x @ Wh
    bf16x3_gemm<<<dim3(2, 64, 1), 256>>>(x, WhT, support, NN, DHID, DIN, DIN);
    transpose_k<<<dim3(DHID / 32, NN / 32), dim3(32, 8)>>>(support, supT, NN, DHID);

    // hidden = relu(adj @ support), split-K 2
    bf16x3_gemm<<<dim3(2, 64, 2), 256>>>(adj, supT, part, NN, DHID, NN, NN / 2);
    reduce2_relu<<<(NN * DHID / 4 + 255) / 256, 256>>>(part, part + (size_t)NN * DHID,
                                                       hidden, NN * DHID / 4);

    // s = hidden @ [Wm|Wl]
    bf16x3_gemm<<<dim3(1, 64, 1), 256>>>(hidden, WcT, sbuf, NN, DCAT, DHID, DHID);
    transpose_k<<<dim3(DCAT / 32, NN / 32), dim3(32, 8)>>>(sbuf, sT, NN, DCAT);

    // zcat = adj @ s, split-K 2 -> z_mean, z_log_std
    bf16x3_gemm<<<dim3(1, 64, 2), 256>>>(adj, sT, part, NN, DCAT, NN, NN / 2);
    reduce2_split<<<(NN * DCAT / 4 + 255) / 256, 256>>>(part, part + (size_t)NN * DCAT,
                                                        zm, zl);

    // recon = z_mean @ z_mean^T
    bf16x3_gemm<<<dim3(64, 64, 1), 256>>>(zm, zm, recon, NN, NN, DZ, DZ);
}

// round 9
// speedup vs baseline: 2.5137x; 1.1093x over previous
#include <cuda_runtime.h>
#include <cuda_bf16.h>
#include <cstdint>

// ---------------------------------------------------------------------------
// GCNModelVAE forward — bf16 mma.sync GEMMs with 3-term error compensation.
// (tcgen05 unavailable: harness ptxas targets plain sm_103)
//   support = x @ Wh                  [8192,512]@[512,256]
//   hidden  = relu(adj @ support)     [8192,8192]@[8192,256]  split-K 2
//   s       = hidden @ [Wm|Wl]        [8192,256]@[256,128]
//   zcat    = adj @ s                 [8192,8192]@[8192,128]  split-K 2
//   recon   = z_mean @ z_mean^T       [8192,64] rank-k
// Output: [recon | z_mean | z_log_std]
//
// Compensation: a = ah + al (bf16 hi + bf16 residual);
//   C = Ah*Bl + Al*Bh + Ah*Bh   (Al*Bl ~2^-18 dropped) -> ~1e-5 per GEMM.
// R9 changes: 2-stage smem double buffer, ONE barrier per k-tile (conversion
// overlaps other warps' mma), shift/mask hi-extraction instead of cvt pairs.
// ---------------------------------------------------------------------------

#define NN   8192
#define DIN  512
#define DHID 256
#define DZ   64
#define DCAT 128

// ---- scratch (allocation-free) ----
#define OFF_SUPPORT 0
#define OFF_SUPT    (OFF_SUPPORT + NN*DHID)
#define OFF_HIDDEN  (OFF_SUPT    + NN*DHID)
#define OFF_PART    (OFF_HIDDEN  + NN*DHID)
#define OFF_S       (OFF_PART    + 2*NN*DHID)
#define OFF_ST      (OFF_S       + NN*DCAT)
#define OFF_WHT     (OFF_ST      + NN*DCAT)
#define OFF_WCT     (OFF_WHT     + DIN*DHID)
#define SZ_TOTAL    (OFF_WCT     + DHID*DCAT)

__device__ __align__(16) float g_scratch[SZ_TOTAL];

// ---------------------------------------------------------------------------
// helpers
// ---------------------------------------------------------------------------
__device__ __forceinline__ uint32_t smem_u32(const void* p) {
    uint32_t a;
    asm("{ .reg .u64 t; cvta.to.shared.u64 t, %1; cvt.u32.u64 %0, t; }"
        : "=r"(a) : "l"(p));
    return a;
}

// pack (lo, hi) floats -> bf16x2 (lo in low 16 bits), round-to-nearest
__device__ __forceinline__ uint32_t pack_bf2(float lo, float hi) {
    uint32_t r;
    asm("cvt.rn.bf16x2.f32 %0, %1, %2;" : "=r"(r) : "f"(hi), "f"(lo));
    return r;
}

__device__ __forceinline__ void ldm_x4(uint32_t* r, uint32_t addr) {
    asm volatile("ldmatrix.sync.aligned.m8n8.x4.shared.b16 {%0,%1,%2,%3}, [%4];"
                 : "=r"(r[0]), "=r"(r[1]), "=r"(r[2]), "=r"(r[3]) : "r"(addr));
}

__device__ __forceinline__ void mma_bf16(float* c, const uint32_t* a, const uint32_t* b) {
    asm volatile(
        "mma.sync.aligned.m16n8k16.row.col.f32.bf16.bf16.f32 "
        "{%0,%1,%2,%3}, {%4,%5,%6,%7}, {%8,%9}, {%0,%1,%2,%3};"
        : "+f"(c[0]), "+f"(c[1]), "+f"(c[2]), "+f"(c[3])
        : "r"(a[0]), "r"(a[1]), "r"(a[2]), "r"(a[3]), "r"(b[0]), "r"(b[1]));
}

// split float4 v -> packed bf16 hi pair (hp) and residual pair (lp).
// hi floats recovered from the packed bf16x2 by shift/mask (no extra cvts).
__device__ __forceinline__ void split_pack(float4 v, uint2& hp, uint2& lp) {
    hp.x = pack_bf2(v.x, v.y);
    hp.y = pack_bf2(v.z, v.w);
    float h0 = __uint_as_float(hp.x << 16);
    float h1 = __uint_as_float(hp.x & 0xffff0000u);
    float h2 = __uint_as_float(hp.y << 16);
    float h3 = __uint_as_float(hp.y & 0xffff0000u);
    lp.x = pack_bf2(v.x - h0, v.y - h1);
    lp.y = pack_bf2(v.z - h2, v.w - h3);
}

// ---------------------------------------------------------------------------
// bf16x3 GEMM: C[M,N] (split-K slice z at C + z*M*N) = A[M,K] @ BT[N,K]^T.
// BM=BN=128, BK=32 fp32. 256 threads, warp grid 4(m) x 2(n), warp tile 32x64.
// Smem: per stage 4 bf16 tiles (Ah, Al, Bl, Bh), 128 rows x 64B data, 80B
// pitch (conflict-free ldmatrix). 2 stages, ONE __syncthreads per k-tile.
// grid=(N/128, M/128, K/kChunk).
// ---------------------------------------------------------------------------
#define PITCH   80
#define SEGSZ   (128 * PITCH)      // 10240
#define SEG_AH  0
#define SEG_AL  (1 * SEGSZ)
#define SEG_BL  (2 * SEGSZ)
#define SEG_BH  (3 * SEGSZ)
#define GSTAGE  (4 * SEGSZ)        // 40960 per stage
#define GEMM_SMEM (2 * GSTAGE)     // 81920

__global__ void __launch_bounds__(256, 1)
bf16x3_gemm(const float* __restrict__ A, const float* __restrict__ BT,
            float* __restrict__ C, int M, int N, int K, int kChunk)
{
    extern __shared__ __align__(16) char sm[];
    const uint32_t smb = smem_u32(sm);

    const int tid = threadIdx.x;
    const int wid = tid >> 5;
    const int lane = tid & 31;
    const int warp_m = wid & 3;        // 4 warps over M (32 rows each)
    const int warp_n = wid >> 2;       // 2 warps over N (64 cols each)

    const int m0 = blockIdx.y * 128;
    const int n0 = blockIdx.x * 128;
    const int kBeg = blockIdx.z * kChunk;
    const int nkt = kChunk >> 5;
    float* Cout = C + (size_t)blockIdx.z * (size_t)M * (size_t)N;

    float acc[2][8][4];
#pragma unroll
    for (int mt = 0; mt < 2; mt++)
#pragma unroll
        for (int nf = 0; nf < 8; nf++)
#pragma unroll
            for (int e = 0; e < 4; e++) acc[mt][nf][e] = 0.f;

    // tile loaders: thread -> (row = lr + 32i, k-float4 = c4)
    const int lr = tid >> 3;
    const int c4 = tid & 7;
    const float* Ab = A + (size_t)(m0 + lr) * (size_t)K + c4 * 4;
    const float* Bb = BT + (size_t)(n0 + lr) * (size_t)K + c4 * 4;
    const uint32_t stoff = (uint32_t)(lr * PITCH + c4 * 8);

    float4 ra[4], rb[4];
#pragma unroll
    for (int i = 0; i < 4; i++) {
        ra[i] = *(const float4*)(Ab + (size_t)(i * 32) * (size_t)K + kBeg);
        rb[i] = *(const float4*)(Bb + (size_t)(i * 32) * (size_t)K + kBeg);
    }

    // precomputed ldmatrix address components
    const uint32_t a_row = (uint32_t)(warp_m * 32 + (lane & 15));
    const uint32_t a_off = a_row * PITCH + ((uint32_t)(lane >> 4) << 4);
    const uint32_t b_row = (uint32_t)(warp_n * 64 + (lane & 7) + ((lane >> 4) << 3));
    const uint32_t b_off = b_row * PITCH + (((uint32_t)(lane >> 3) & 1) << 4);

    for (int kt = 0; kt < nkt; kt++) {
        const uint32_t stg = (uint32_t)(kt & 1) * GSTAGE;
        char* sp = sm + stg;

        // ---- convert + store tile into stage (overlaps other warps' mma) ----
#pragma unroll
        for (int i = 0; i < 4; i++) {
            const uint32_t off = stoff + (uint32_t)(i * 32 * PITCH);
            uint2 hp, lp;
            split_pack(ra[i], hp, lp);
            *(uint2*)(sp + SEG_AH + off) = hp;
            *(uint2*)(sp + SEG_AL + off) = lp;
            split_pack(rb[i], hp, lp);
            *(uint2*)(sp + SEG_BH + off) = hp;
            *(uint2*)(sp + SEG_BL + off) = lp;
        }
        __syncthreads();

        // ---- prefetch next tile (hides LDG behind mma) ----
        if (kt + 1 < nkt) {
            const int k0 = kBeg + ((kt + 1) << 5);
#pragma unroll
            for (int i = 0; i < 4; i++) {
                ra[i] = *(const float4*)(Ab + (size_t)(i * 32) * (size_t)K + k0);
                rb[i] = *(const float4*)(Bb + (size_t)(i * 32) * (size_t)K + k0);
            }
        }

        // ---- compute: 2 k16 steps x 3 compensation passes ----
        const uint32_t sa = smb + stg + a_off;
        const uint32_t sb = smb + stg + b_off;
#pragma unroll
        for (int kk = 0; kk < 2; kk++) {
            const uint32_t kb = (uint32_t)(kk * 32);
            uint32_t Ah[2][4], Al[2][4];
#pragma unroll
            for (int mt = 0; mt < 2; mt++) {
                const uint32_t base = sa + (uint32_t)(mt * 16 * PITCH) + kb;
                ldm_x4(Ah[mt], base + SEG_AH);
                ldm_x4(Al[mt], base + SEG_AL);
            }
            uint32_t B[8][2];
            // pass 0: Ah * Bl
#pragma unroll
            for (int nf2 = 0; nf2 < 4; nf2++) {
                uint32_t t[4];
                ldm_x4(t, sb + SEG_BL + (uint32_t)(nf2 * 16 * PITCH) + kb);
                B[2 * nf2][0] = t[0]; B[2 * nf2][1] = t[1];
                B[2 * nf2 + 1][0] = t[2]; B[2 * nf2 + 1][1] = t[3];
            }
#pragma unroll
            for (int mt = 0; mt < 2; mt++)
#pragma unroll
                for (int nf = 0; nf < 8; nf++)
                    mma_bf16(acc[mt][nf], Ah[mt], B[nf]);
            // passes 1+2: Al * Bh, Ah * Bh
#pragma unroll
            for (int nf2 = 0; nf2 < 4; nf2++) {
                uint32_t t[4];
                ldm_x4(t, sb + SEG_BH + (uint32_t)(nf2 * 16 * PITCH) + kb);
                B[2 * nf2][0] = t[0]; B[2 * nf2][1] = t[1];
                B[2 * nf2 + 1][0] = t[2]; B[2 * nf2 + 1][1] = t[3];
            }
#pragma unroll
            for (int mt = 0; mt < 2; mt++)
#pragma unroll
                for (int nf = 0; nf < 8; nf++) {
                    mma_bf16(acc[mt][nf], Al[mt], B[nf]);
                    mma_bf16(acc[mt][nf], Ah[mt], B[nf]);
                }
        }
        // NOTE: no trailing barrier — next iteration's STS targets the OTHER
        // stage; mma(kt-1) on that stage completed before this tile's barrier.
    }

    // ---- epilogue ----
    const int erow = m0 + warp_m * 32 + (lane >> 2);
    const int ecol = n0 + warp_n * 64 + 2 * (lane & 3);
#pragma unroll
    for (int mt = 0; mt < 2; mt++) {
#pragma unroll
        for (int nf = 0; nf < 8; nf++) {
            float* p0 = Cout + (size_t)(erow + mt * 16) * (size_t)N + ecol + nf * 8;
            float* p1 = p0 + (size_t)8 * (size_t)N;
            *(float2*)p0 = make_float2(acc[mt][nf][0], acc[mt][nf][1]);
            *(float2*)p1 = make_float2(acc[mt][nf][2], acc[mt][nf][3]);
        }
    }
}

// ---------------------------------------------------------------------------
// helpers: transpose, pack, reduces
// ---------------------------------------------------------------------------
__global__ void transpose_k(const float* __restrict__ in, float* __restrict__ out,
                            int R, int C) {
    __shared__ float t[32][33];
    const int c0 = blockIdx.x * 32, r0 = blockIdx.y * 32;
    const int tx = threadIdx.x, ty = threadIdx.y;
#pragma unroll
    for (int j = 0; j < 4; j++)
        t[ty + j * 8][tx] = in[(size_t)(r0 + ty + j * 8) * (size_t)C + c0 + tx];
    __syncthreads();
#pragma unroll
    for (int j = 0; j < 4; j++)
        out[(size_t)(c0 + ty + j * 8) * (size_t)R + r0 + tx] = t[tx][ty + j * 8];
}

// WcT[c][r] = c<64 ? Wm[r][c] : Wl[r][c-64];  WcT is [128,256]
__global__ void pack_wct(const float* __restrict__ Wm, const float* __restrict__ Wl,
                         float* __restrict__ WcT) {
    int i = blockIdx.x * blockDim.x + threadIdx.x;    // 128*256
    if (i >= DCAT * DHID) return;
    int c = i >> 8, r = i & 255;
    WcT[i] = (c < DZ) ? Wm[r * DZ + c] : Wl[r * DZ + (c - DZ)];
}

__global__ void reduce2_relu(const float* __restrict__ p0, const float* __restrict__ p1,
                             float* __restrict__ out, int n4) {
    int i = blockIdx.x * blockDim.x + threadIdx.x;
    if (i >= n4) return;
    float4 a = ((const float4*)p0)[i];
    float4 b = ((const float4*)p1)[i];
    float4 r;
    r.x = fmaxf(a.x + b.x, 0.f);
    r.y = fmaxf(a.y + b.y, 0.f);
    r.z = fmaxf(a.z + b.z, 0.f);
    r.w = fmaxf(a.w + b.w, 0.f);
    ((float4*)out)[i] = r;
}

// zcat = p0+p1; split cols [0,64)->zm, [64,128)->zl
__global__ void reduce2_split(const float* __restrict__ p0, const float* __restrict__ p1,
                              float* __restrict__ zm, float* __restrict__ zl) {
    int i = blockIdx.x * blockDim.x + threadIdx.x;    // NN*DCAT/4
    if (i >= NN * DCAT / 4) return;
    int row = i >> 5, c4 = i & 31;
    float4 a = ((const float4*)p0)[i];
    float4 b = ((const float4*)p1)[i];
    float4 r = make_float4(a.x + b.x, a.y + b.y, a.z + b.z, a.w + b.w);
    if (c4 < 16) ((float4*)zm)[(size_t)row * 16 + c4] = r;
    else         ((float4*)zl)[(size_t)row * 16 + (c4 - 16)] = r;
}

// ---------------------------------------------------------------------------
extern "C" void kernel_launch(void* const* d_in, const int* in_sizes, int n_in,
                              void* d_out, int out_size) {
    const float* x = nullptr;
    const float* adj = nullptr;
    const float* Wh = nullptr;
    const float* Wsmall[2] = {nullptr, nullptr};
    int nsmall = 0;
    for (int i = 0; i < n_in; i++) {
        const float* p = (const float*)d_in[i];
        switch (in_sizes[i]) {
            case NN * DIN:   x = p; break;
            case NN * NN:    adj = p; break;
            case DIN * DHID: Wh = p; break;
            case DHID * DZ:  if (nsmall < 2) Wsmall[nsmall++] = p; break;
            default: break;
        }
    }
    const float* Wm = Wsmall[0];
    const float* Wl = Wsmall[1];

    float* out = (float*)d_out;
    float* recon = out;
    float* zm = out + (size_t)NN * (size_t)NN;
    float* zl = zm + (size_t)NN * (size_t)DZ;

    float* ws = nullptr;
    cudaGetSymbolAddress((void**)&ws, g_scratch);
    float* support = ws + OFF_SUPPORT;
    float* supT    = ws + OFF_SUPT;
    float* hidden  = ws + OFF_HIDDEN;
    float* part    = ws + OFF_PART;
    float* sbuf    = ws + OFF_S;
    float* sT      = ws + OFF_ST;
    float* WhT     = ws + OFF_WHT;
    float* WcT     = ws + OFF_WCT;

    cudaFuncSetAttribute(bf16x3_gemm, cudaFuncAttributeMaxDynamicSharedMemorySize,
                         GEMM_SMEM);

    // weights -> K-major
    transpose_k<<<dim3(DHID / 32, DIN / 32), dim3(32, 8)>>>(Wh, WhT, DIN, DHID);
    pack_wct<<<(DCAT * DHID + 255) / 256, 256>>>(Wm, Wl, WcT);

    // support = x @ Wh
    bf16x3_gemm<<<dim3(2, 64, 1), 256, GEMM_SMEM>>>(x, WhT, support, NN, DHID, DIN, DIN);
    transpose_k<<<dim3(DHID / 32, NN / 32), dim3(32, 8)>>>(support, supT, NN, DHID);

    // hidden = relu(adj @ support), split-K 2
    bf16x3_gemm<<<dim3(2, 64, 2), 256, GEMM_SMEM>>>(adj, supT, part, NN, DHID, NN, NN / 2);
    reduce2_relu<<<(NN * DHID / 4 + 255) / 256, 256>>>(part, part + (size_t)NN * DHID,
                                                       hidden, NN * DHID / 4);

    // s = hidden @ [Wm|Wl]
    bf16x3_gemm<<<dim3(1, 64, 1), 256, GEMM_SMEM>>>(hidden, WcT, sbuf, NN, DCAT, DHID, DHID);
    transpose_k<<<dim3(DCAT / 32, NN / 32), dim3(32, 8)>>>(sbuf, sT, NN, DCAT);

    // zcat = adj @ s, split-K 2 -> z_mean, z_log_std
    bf16x3_gemm<<<dim3(1, 64, 2), 256, GEMM_SMEM>>>(adj, sT, part, NN, DCAT, NN, NN / 2);
    reduce2_split<<<(NN * DCAT / 4 + 255) / 256, 256>>>(part, part + (size_t)NN * DCAT,
                                                        zm, zl);

    // recon = z_mean @ z_mean^T
    bf16x3_gemm<<<dim3(64, 64, 1), 256, GEMM_SMEM>>>(zm, zm, recon, NN, NN, DZ, DZ);
}

// round 10
// speedup vs baseline: 2.5997x; 1.0343x over previous
#include <cuda_runtime.h>
#include <cuda_bf16.h>
#include <cstdint>

// ---------------------------------------------------------------------------
// GCNModelVAE forward — bf16 mma.sync GEMMs with 3-term error compensation.
// (tcgen05 unavailable: harness ptxas targets plain sm_103)
//   support = x @ Wh                  [8192,512]@[512,256]
//   hidden  = relu(adj @ support)     [8192,8192]@[8192,256]  split-K 2
//   s       = hidden @ [Wm|Wl]        [8192,256]@[256,128]
//   zcat    = adj @ s                 [8192,8192]@[8192,128]  split-K 4
//   recon   = z_mean @ z_mean^T       [8192,64] rank-k
// Output: [recon | z_mean | z_log_std]
//
// Compensation: a = ah + al (bf16 hi + bf16 residual);
//   C = Ah*Bl + Al*Bh + Ah*Bh   (Al*Bl ~2^-18 dropped) -> ~1e-5 per GEMM.
// R10 changes: occupancy 2 (launch_bounds(256,2); no gmem register prefetch —
// the co-resident CTA hides LDG latency), G2 split-K 4 so 256 CTAs fill the
// occ-2 wave, fused reduce4_split.
// ---------------------------------------------------------------------------

#define NN   8192
#define DIN  512
#define DHID 256
#define DZ   64
#define DCAT 128

// ---- scratch (allocation-free) ----
#define OFF_SUPPORT 0
#define OFF_SUPT    (OFF_SUPPORT + NN*DHID)
#define OFF_HIDDEN  (OFF_SUPT    + NN*DHID)
#define OFF_PART    (OFF_HIDDEN  + NN*DHID)
#define OFF_S       (OFF_PART    + 4*NN*DHID)
#define OFF_ST      (OFF_S       + NN*DCAT)
#define OFF_WHT     (OFF_ST      + NN*DCAT)
#define OFF_WCT     (OFF_WHT     + DIN*DHID)
#define SZ_TOTAL    (OFF_WCT     + DHID*DCAT)

__device__ __align__(16) float g_scratch[SZ_TOTAL];

// ---------------------------------------------------------------------------
// helpers
// ---------------------------------------------------------------------------
__device__ __forceinline__ uint32_t smem_u32(const void* p) {
    uint32_t a;
    asm("{ .reg .u64 t; cvta.to.shared.u64 t, %1; cvt.u32.u64 %0, t; }"
        : "=r"(a) : "l"(p));
    return a;
}

// pack (lo, hi) floats -> bf16x2 (lo in low 16 bits), round-to-nearest
__device__ __forceinline__ uint32_t pack_bf2(float lo, float hi) {
    uint32_t r;
    asm("cvt.rn.bf16x2.f32 %0, %1, %2;" : "=r"(r) : "f"(hi), "f"(lo));
    return r;
}

__device__ __forceinline__ void ldm_x4(uint32_t* r, uint32_t addr) {
    asm volatile("ldmatrix.sync.aligned.m8n8.x4.shared.b16 {%0,%1,%2,%3}, [%4];"
                 : "=r"(r[0]), "=r"(r[1]), "=r"(r[2]), "=r"(r[3]) : "r"(addr));
}

__device__ __forceinline__ void mma_bf16(float* c, const uint32_t* a, const uint32_t* b) {
    asm volatile(
        "mma.sync.aligned.m16n8k16.row.col.f32.bf16.bf16.f32 "
        "{%0,%1,%2,%3}, {%4,%5,%6,%7}, {%8,%9}, {%0,%1,%2,%3};"
        : "+f"(c[0]), "+f"(c[1]), "+f"(c[2]), "+f"(c[3])
        : "r"(a[0]), "r"(a[1]), "r"(a[2]), "r"(a[3]), "r"(b[0]), "r"(b[1]));
}

// split float4 v -> packed bf16 hi pair (hp) and residual pair (lp).
// hi floats recovered from the packed bf16x2 by shift/mask (no extra cvts).
__device__ __forceinline__ void split_pack(float4 v, uint2& hp, uint2& lp) {
    hp.x = pack_bf2(v.x, v.y);
    hp.y = pack_bf2(v.z, v.w);
    float h0 = __uint_as_float(hp.x << 16);
    float h1 = __uint_as_float(hp.x & 0xffff0000u);
    float h2 = __uint_as_float(hp.y << 16);
    float h3 = __uint_as_float(hp.y & 0xffff0000u);
    lp.x = pack_bf2(v.x - h0, v.y - h1);
    lp.y = pack_bf2(v.z - h2, v.w - h3);
}

// ---------------------------------------------------------------------------
// bf16x3 GEMM: C[M,N] (split-K slice z at C + z*M*N) = A[M,K] @ BT[N,K]^T.
// BM=BN=128, BK=32 fp32. 256 threads, warp grid 4(m) x 2(n), warp tile 32x64.
// Smem: per stage 4 bf16 tiles (Ah, Al, Bl, Bh), 128 rows x 64B data, 80B
// pitch (conflict-free ldmatrix). 2 stages, ONE __syncthreads per k-tile.
// Occupancy 2: co-resident CTA hides this CTA's LDG/convert phase.
// grid=(N/128, M/128, K/kChunk).
// ---------------------------------------------------------------------------
#define PITCH   80
#define SEGSZ   (128 * PITCH)      // 10240
#define SEG_AH  0
#define SEG_AL  (1 * SEGSZ)
#define SEG_BL  (2 * SEGSZ)
#define SEG_BH  (3 * SEGSZ)
#define GSTAGE  (4 * SEGSZ)        // 40960 per stage
#define GEMM_SMEM (2 * GSTAGE)     // 81920

__global__ void __launch_bounds__(256, 2)
bf16x3_gemm(const float* __restrict__ A, const float* __restrict__ BT,
            float* __restrict__ C, int M, int N, int K, int kChunk)
{
    extern __shared__ __align__(16) char sm[];
    const uint32_t smb = smem_u32(sm);

    const int tid = threadIdx.x;
    const int wid = tid >> 5;
    const int lane = tid & 31;
    const int warp_m = wid & 3;        // 4 warps over M (32 rows each)
    const int warp_n = wid >> 2;       // 2 warps over N (64 cols each)

    const int m0 = blockIdx.y * 128;
    const int n0 = blockIdx.x * 128;
    const int kBeg = blockIdx.z * kChunk;
    const int nkt = kChunk >> 5;
    float* Cout = C + (size_t)blockIdx.z * (size_t)M * (size_t)N;

    float acc[2][8][4];
#pragma unroll
    for (int mt = 0; mt < 2; mt++)
#pragma unroll
        for (int nf = 0; nf < 8; nf++)
#pragma unroll
            for (int e = 0; e < 4; e++) acc[mt][nf][e] = 0.f;

    // tile loaders: thread -> (row = lr + 32i, k-float4 = c4)
    const int lr = tid >> 3;
    const int c4 = tid & 7;
    const float* Ab = A + (size_t)(m0 + lr) * (size_t)K + c4 * 4;
    const float* Bb = BT + (size_t)(n0 + lr) * (size_t)K + c4 * 4;
    const uint32_t stoff = (uint32_t)(lr * PITCH + c4 * 8);

    // precomputed ldmatrix address components
    const uint32_t a_row = (uint32_t)(warp_m * 32 + (lane & 15));
    const uint32_t a_off = a_row * PITCH + ((uint32_t)(lane >> 4) << 4);
    const uint32_t b_row = (uint32_t)(warp_n * 64 + (lane & 7) + ((lane >> 4) << 3));
    const uint32_t b_off = b_row * PITCH + (((uint32_t)(lane >> 3) & 1) << 4);

    for (int kt = 0; kt < nkt; kt++) {
        const uint32_t stg = (uint32_t)(kt & 1) * GSTAGE;
        char* sp = sm + stg;
        const int k0 = kBeg + (kt << 5);

        // ---- load + convert + store tile (co-resident CTA hides latency) ----
#pragma unroll
        for (int i = 0; i < 4; i++) {
            const uint32_t off = stoff + (uint32_t)(i * 32 * PITCH);
            float4 va = *(const float4*)(Ab + (size_t)(i * 32) * (size_t)K + k0);
            float4 vb = *(const float4*)(Bb + (size_t)(i * 32) * (size_t)K + k0);
            uint2 hp, lp;
            split_pack(va, hp, lp);
            *(uint2*)(sp + SEG_AH + off) = hp;
            *(uint2*)(sp + SEG_AL + off) = lp;
            split_pack(vb, hp, lp);
            *(uint2*)(sp + SEG_BH + off) = hp;
            *(uint2*)(sp + SEG_BL + off) = lp;
        }
        __syncthreads();

        // ---- compute: 2 k16 steps x 3 compensation passes ----
        const uint32_t sa = smb + stg + a_off;
        const uint32_t sb = smb + stg + b_off;
#pragma unroll
        for (int kk = 0; kk < 2; kk++) {
            const uint32_t kb = (uint32_t)(kk * 32);
            uint32_t Ah[2][4], Al[2][4];
#pragma unroll
            for (int mt = 0; mt < 2; mt++) {
                const uint32_t base = sa + (uint32_t)(mt * 16 * PITCH) + kb;
                ldm_x4(Ah[mt], base + SEG_AH);
                ldm_x4(Al[mt], base + SEG_AL);
            }
            uint32_t B[8][2];
            // pass 0: Ah * Bl
#pragma unroll
            for (int nf2 = 0; nf2 < 4; nf2++) {
                uint32_t t[4];
                ldm_x4(t, sb + SEG_BL + (uint32_t)(nf2 * 16 * PITCH) + kb);
                B[2 * nf2][0] = t[0]; B[2 * nf2][1] = t[1];
                B[2 * nf2 + 1][0] = t[2]; B[2 * nf2 + 1][1] = t[3];
            }
#pragma unroll
            for (int mt = 0; mt < 2; mt++)
#pragma unroll
                for (int nf = 0; nf < 8; nf++)
                    mma_bf16(acc[mt][nf], Ah[mt], B[nf]);
            // passes 1+2: Al * Bh, Ah * Bh
#pragma unroll
            for (int nf2 = 0; nf2 < 4; nf2++) {
                uint32_t t[4];
                ldm_x4(t, sb + SEG_BH + (uint32_t)(nf2 * 16 * PITCH) + kb);
                B[2 * nf2][0] = t[0]; B[2 * nf2][1] = t[1];
                B[2 * nf2 + 1][0] = t[2]; B[2 * nf2 + 1][1] = t[3];
            }
#pragma unroll
            for (int mt = 0; mt < 2; mt++)
#pragma unroll
                for (int nf = 0; nf < 8; nf++) {
                    mma_bf16(acc[mt][nf], Al[mt], B[nf]);
                    mma_bf16(acc[mt][nf], Ah[mt], B[nf]);
                }
        }
        // no trailing barrier: next STS targets the OTHER stage; mma(kt-1) on
        // that stage completed before this tile's barrier in every warp.
    }

    // ---- epilogue ----
    const int erow = m0 + warp_m * 32 + (lane >> 2);
    const int ecol = n0 + warp_n * 64 + 2 * (lane & 3);
#pragma unroll
    for (int mt = 0; mt < 2; mt++) {
#pragma unroll
        for (int nf = 0; nf < 8; nf++) {
            float* p0 = Cout + (size_t)(erow + mt * 16) * (size_t)N + ecol + nf * 8;
            float* p1 = p0 + (size_t)8 * (size_t)N;
            *(float2*)p0 = make_float2(acc[mt][nf][0], acc[mt][nf][1]);
            *(float2*)p1 = make_float2(acc[mt][nf][2], acc[mt][nf][3]);
        }
    }
}

// ---------------------------------------------------------------------------
// helpers: transpose, pack, reduces
// ---------------------------------------------------------------------------
__global__ void transpose_k(const float* __restrict__ in, float* __restrict__ out,
                            int R, int C) {
    __shared__ float t[32][33];
    const int c0 = blockIdx.x * 32, r0 = blockIdx.y * 32;
    const int tx = threadIdx.x, ty = threadIdx.y;
#pragma unroll
    for (int j = 0; j < 4; j++)
        t[ty + j * 8][tx] = in[(size_t)(r0 + ty + j * 8) * (size_t)C + c0 + tx];
    __syncthreads();
#pragma unroll
    for (int j = 0; j < 4; j++)
        out[(size_t)(c0 + ty + j * 8) * (size_t)R + r0 + tx] = t[tx][ty + j * 8];
}

// WcT[c][r] = c<64 ? Wm[r][c] : Wl[r][c-64];  WcT is [128,256]
__global__ void pack_wct(const float* __restrict__ Wm, const float* __restrict__ Wl,
                         float* __restrict__ WcT) {
    int i = blockIdx.x * blockDim.x + threadIdx.x;    // 128*256
    if (i >= DCAT * DHID) return;
    int c = i >> 8, r = i & 255;
    WcT[i] = (c < DZ) ? Wm[r * DZ + c] : Wl[r * DZ + (c - DZ)];
}

__global__ void reduce2_relu(const float* __restrict__ p0, const float* __restrict__ p1,
                             float* __restrict__ out, int n4) {
    int i = blockIdx.x * blockDim.x + threadIdx.x;
    if (i >= n4) return;
    float4 a = ((const float4*)p0)[i];
    float4 b = ((const float4*)p1)[i];
    float4 r;
    r.x = fmaxf(a.x + b.x, 0.f);
    r.y = fmaxf(a.y + b.y, 0.f);
    r.z = fmaxf(a.z + b.z, 0.f);
    r.w = fmaxf(a.w + b.w, 0.f);
    ((float4*)out)[i] = r;
}

// zcat = p0+p1+p2+p3; split cols [0,64)->zm, [64,128)->zl
__global__ void reduce4_split(const float* __restrict__ p, size_t stride,
                              float* __restrict__ zm, float* __restrict__ zl) {
    int i = blockIdx.x * blockDim.x + threadIdx.x;    // NN*DCAT/4
    if (i >= NN * DCAT / 4) return;
    int row = i >> 5, c4 = i & 31;
    float4 a = ((const float4*)p)[i];
    float4 b = ((const float4*)(p + stride))[i];
    float4 c = ((const float4*)(p + 2 * stride))[i];
    float4 d = ((const float4*)(p + 3 * stride))[i];
    float4 r = make_float4(a.x + b.x + c.x + d.x, a.y + b.y + c.y + d.y,
                           a.z + b.z + c.z + d.z, a.w + b.w + c.w + d.w);
    if (c4 < 16) ((float4*)zm)[(size_t)row * 16 + c4] = r;
    else         ((float4*)zl)[(size_t)row * 16 + (c4 - 16)] = r;
}

// ---------------------------------------------------------------------------
extern "C" void kernel_launch(void* const* d_in, const int* in_sizes, int n_in,
                              void* d_out, int out_size) {
    const float* x = nullptr;
    const float* adj = nullptr;
    const float* Wh = nullptr;
    const float* Wsmall[2] = {nullptr, nullptr};
    int nsmall = 0;
    for (int i = 0; i < n_in; i++) {
        const float* p = (const float*)d_in[i];
        switch (in_sizes[i]) {
            case NN * DIN:   x = p; break;
            case NN * NN:    adj = p; break;
            case DIN * DHID: Wh = p; break;
            case DHID * DZ:  if (nsmall < 2) Wsmall[nsmall++] = p; break;
            default: break;
        }
    }
    const float* Wm = Wsmall[0];
    const float* Wl = Wsmall[1];

    float* out = (float*)d_out;
    float* recon = out;
    float* zm = out + (size_t)NN * (size_t)NN;
    float* zl = zm + (size_t)NN * (size_t)DZ;

    float* ws = nullptr;
    cudaGetSymbolAddress((void**)&ws, g_scratch);
    float* support = ws + OFF_SUPPORT;
    float* supT    = ws + OFF_SUPT;
    float* hidden  = ws + OFF_HIDDEN;
    float* part    = ws + OFF_PART;
    float* sbuf    = ws + OFF_S;
    float* sT      = ws + OFF_ST;
    float* WhT     = ws + OFF_WHT;
    float* WcT     = ws + OFF_WCT;

    cudaFuncSetAttribute(bf16x3_gemm, cudaFuncAttributeMaxDynamicSharedMemorySize,
                         GEMM_SMEM);

    // weights -> K-major
    transpose_k<<<dim3(DHID / 32, DIN / 32), dim3(32, 8)>>>(Wh, WhT, DIN, DHID);
    pack_wct<<<(DCAT * DHID + 255) / 256, 256>>>(Wm, Wl, WcT);

    // support = x @ Wh
    bf16x3_gemm<<<dim3(2, 64, 1), 256, GEMM_SMEM>>>(x, WhT, support, NN, DHID, DIN, DIN);
    transpose_k<<<dim3(DHID / 32, NN / 32), dim3(32, 8)>>>(support, supT, NN, DHID);

    // hidden = relu(adj @ support), split-K 2 (256 CTAs = one occ-2 wave)
    bf16x3_gemm<<<dim3(2, 64, 2), 256, GEMM_SMEM>>>(adj, supT, part, NN, DHID, NN, NN / 2);
    reduce2_relu<<<(NN * DHID / 4 + 255) / 256, 256>>>(part, part + (size_t)NN * DHID,
                                                       hidden, NN * DHID / 4);

    // s = hidden @ [Wm|Wl]
    bf16x3_gemm<<<dim3(1, 64, 1), 256, GEMM_SMEM>>>(hidden, WcT, sbuf, NN, DCAT, DHID, DHID);
    transpose_k<<<dim3(DCAT / 32, NN / 32), dim3(32, 8)>>>(sbuf, sT, NN, DCAT);

    // zcat = adj @ s, split-K 4 (256 CTAs) -> z_mean, z_log_std
    bf16x3_gemm<<<dim3(1, 64, 4), 256, GEMM_SMEM>>>(adj, sT, part, NN, DCAT, NN, NN / 4);
    reduce4_split<<<(NN * DCAT / 4 + 255) / 256, 256>>>(part, (size_t)NN * DCAT, zm, zl);

    // recon = z_mean @ z_mean^T
    bf16x3_gemm<<<dim3(64, 64, 1), 256, GEMM_SMEM>>>(zm, zm, recon, NN, NN, DZ, DZ);
}

// round 11
// speedup vs baseline: 2.6819x; 1.0316x over previous
#include <cuda_runtime.h>
#include <cuda_bf16.h>
#include <cstdint>

// ---------------------------------------------------------------------------
// GCNModelVAE forward — bf16 mma.sync GEMMs with 3-term error compensation.
// (tcgen05 unavailable: harness ptxas targets plain sm_103)
//   support = x @ Wh                  [8192,512]@[512,256]    split-K 2
//   hidden  = relu(adj @ support)     [8192,8192]@[8192,256]  split-K 8
//   s       = hidden @ [Wm|Wl]        [8192,256]@[256,128]    split-K 4
//   zcat    = adj @ s                 [8192,8192]@[8192,128]  split-K 16
//   recon   = z_mean @ z_mean^T       [8192,64] symmetric rank-k (upper CTAs)
// Output: [recon | z_mean | z_log_std]
//
// Compensation: a = ah + al (bf16 hi + bf16 residual);
//   C = Ah*Bl + Al*Bh + Ah*Bh   (Al*Bl ~2^-18 dropped) -> ~1e-5 per GEMM.
// R11 changes: fine split-K on every GEMM so CTAs/SM is near-integral at occ 2
// (kills the 2:1 wave imbalance), symmetric recon with smem-transposed
// coalesced mirror writes (3-term formula is exactly symmetric).
// ---------------------------------------------------------------------------

#define NN   8192
#define DIN  512
#define DHID 256
#define DZ   64
#define DCAT 128

// ---- scratch (allocation-free) ----
#define SZ_PART     (16*NN*DCAT)      // 16,777,216 floats = 64 MB (max slices)
#define OFF_SUPPORT 0
#define OFF_SUPT    (OFF_SUPPORT + NN*DHID)
#define OFF_HIDDEN  (OFF_SUPT    + NN*DHID)
#define OFF_PART    (OFF_HIDDEN  + NN*DHID)
#define OFF_S       (OFF_PART    + SZ_PART)
#define OFF_ST      (OFF_S       + NN*DCAT)
#define OFF_WHT     (OFF_ST      + NN*DCAT)
#define OFF_WCT     (OFF_WHT     + DIN*DHID)
#define SZ_TOTAL    (OFF_WCT     + DHID*DCAT)

__device__ __align__(16) float g_scratch[SZ_TOTAL];

// ---------------------------------------------------------------------------
// helpers
// ---------------------------------------------------------------------------
__device__ __forceinline__ uint32_t smem_u32(const void* p) {
    uint32_t a;
    asm("{ .reg .u64 t; cvta.to.shared.u64 t, %1; cvt.u32.u64 %0, t; }"
        : "=r"(a) : "l"(p));
    return a;
}

// pack (lo, hi) floats -> bf16x2 (lo in low 16 bits), round-to-nearest
__device__ __forceinline__ uint32_t pack_bf2(float lo, float hi) {
    uint32_t r;
    asm("cvt.rn.bf16x2.f32 %0, %1, %2;" : "=r"(r) : "f"(hi), "f"(lo));
    return r;
}

__device__ __forceinline__ void ldm_x4(uint32_t* r, uint32_t addr) {
    asm volatile("ldmatrix.sync.aligned.m8n8.x4.shared.b16 {%0,%1,%2,%3}, [%4];"
                 : "=r"(r[0]), "=r"(r[1]), "=r"(r[2]), "=r"(r[3]) : "r"(addr));
}

__device__ __forceinline__ void mma_bf16(float* c, const uint32_t* a, const uint32_t* b) {
    asm volatile(
        "mma.sync.aligned.m16n8k16.row.col.f32.bf16.bf16.f32 "
        "{%0,%1,%2,%3}, {%4,%5,%6,%7}, {%8,%9}, {%0,%1,%2,%3};"
        : "+f"(c[0]), "+f"(c[1]), "+f"(c[2]), "+f"(c[3])
        : "r"(a[0]), "r"(a[1]), "r"(a[2]), "r"(a[3]), "r"(b[0]), "r"(b[1]));
}

// split float4 v -> packed bf16 hi pair (hp) and residual pair (lp).
__device__ __forceinline__ void split_pack(float4 v, uint2& hp, uint2& lp) {
    hp.x = pack_bf2(v.x, v.y);
    hp.y = pack_bf2(v.z, v.w);
    float h0 = __uint_as_float(hp.x << 16);
    float h1 = __uint_as_float(hp.x & 0xffff0000u);
    float h2 = __uint_as_float(hp.y << 16);
    float h3 = __uint_as_float(hp.y & 0xffff0000u);
    lp.x = pack_bf2(v.x - h0, v.y - h1);
    lp.y = pack_bf2(v.z - h2, v.w - h3);
}

// ---------------------------------------------------------------------------
// smem layout shared by gemm + syrk
// ---------------------------------------------------------------------------
#define PITCH   80
#define SEGSZ   (128 * PITCH)      // 10240
#define SEG_AH  0
#define SEG_AL  (1 * SEGSZ)
#define SEG_BL  (2 * SEGSZ)
#define SEG_BH  (3 * SEGSZ)
#define GSTAGE  (4 * SEGSZ)        // 40960 per stage
#define GEMM_SMEM (2 * GSTAGE)     // 81920

// core mainloop body (identical in gemm & syrk), expressed as a macro to keep
// both kernels byte-for-byte consistent.
#define MAINLOOP_TILE()                                                        \
    do {                                                                       \
        const uint32_t stg = (uint32_t)(kt & 1) * GSTAGE;                      \
        char* sp = sm + stg;                                                   \
        const int k0 = kBeg + (kt << 5);                                       \
        _Pragma("unroll")                                                      \
        for (int i = 0; i < 4; i++) {                                          \
            const uint32_t off = stoff + (uint32_t)(i * 32 * PITCH);           \
            float4 va = *(const float4*)(Ab + (size_t)(i * 32) * (size_t)K + k0); \
            float4 vb = *(const float4*)(Bb + (size_t)(i * 32) * (size_t)K + k0); \
            uint2 hp, lp;                                                      \
            split_pack(va, hp, lp);                                            \
            *(uint2*)(sp + SEG_AH + off) = hp;                                 \
            *(uint2*)(sp + SEG_AL + off) = lp;                                 \
            split_pack(vb, hp, lp);                                            \
            *(uint2*)(sp + SEG_BH + off) = hp;                                 \
            *(uint2*)(sp + SEG_BL + off) = lp;                                 \
        }                                                                      \
        __syncthreads();                                                       \
        const uint32_t sa = smb + stg + a_off;                                 \
        const uint32_t sb = smb + stg + b_off;                                 \
        _Pragma("unroll")                                                      \
        for (int kk = 0; kk < 2; kk++) {                                       \
            const uint32_t kb = (uint32_t)(kk * 32);                           \
            uint32_t Ah[2][4], Al[2][4];                                       \
            _Pragma("unroll")                                                  \
            for (int mt = 0; mt < 2; mt++) {                                   \
                const uint32_t base = sa + (uint32_t)(mt * 16 * PITCH) + kb;   \
                ldm_x4(Ah[mt], base + SEG_AH);                                 \
                ldm_x4(Al[mt], base + SEG_AL);                                 \
            }                                                                  \
            uint32_t B[8][2];                                                  \
            _Pragma("unroll")                                                  \
            for (int nf2 = 0; nf2 < 4; nf2++) {                                \
                uint32_t t[4];                                                 \
                ldm_x4(t, sb + SEG_BL + (uint32_t)(nf2 * 16 * PITCH) + kb);    \
                B[2 * nf2][0] = t[0]; B[2 * nf2][1] = t[1];                    \
                B[2 * nf2 + 1][0] = t[2]; B[2 * nf2 + 1][1] = t[3];            \
            }                                                                  \
            _Pragma("unroll")                                                  \
            for (int mt = 0; mt < 2; mt++)                                     \
                _Pragma("unroll")                                              \
                for (int nf = 0; nf < 8; nf++)                                 \
                    mma_bf16(acc[mt][nf], Ah[mt], B[nf]);                      \
            _Pragma("unroll")                                                  \
            for (int nf2 = 0; nf2 < 4; nf2++) {                                \
                uint32_t t[4];                                                 \
                ldm_x4(t, sb + SEG_BH + (uint32_t)(nf2 * 16 * PITCH) + kb);    \
                B[2 * nf2][0] = t[0]; B[2 * nf2][1] = t[1];                    \
                B[2 * nf2 + 1][0] = t[2]; B[2 * nf2 + 1][1] = t[3];            \
            }                                                                  \
            _Pragma("unroll")                                                  \
            for (int mt = 0; mt < 2; mt++)                                     \
                _Pragma("unroll")                                              \
                for (int nf = 0; nf < 8; nf++) {                               \
                    mma_bf16(acc[mt][nf], Al[mt], B[nf]);                      \
                    mma_bf16(acc[mt][nf], Ah[mt], B[nf]);                      \
                }                                                              \
        }                                                                      \
    } while (0)

// ---------------------------------------------------------------------------
// bf16x3 GEMM: C[M,N] (split-K slice z at C + z*M*N) = A[M,K] @ BT[N,K]^T.
// BM=BN=128, BK=32 fp32. 256 threads, warp grid 4(m) x 2(n), warp tile 32x64.
// 2 smem stages, ONE __syncthreads per k-tile; occupancy 2.
// grid=(N/128, M/128, K/kChunk).
// ---------------------------------------------------------------------------
__global__ void __launch_bounds__(256, 2)
bf16x3_gemm(const float* __restrict__ A, const float* __restrict__ BT,
            float* __restrict__ C, int M, int N, int K, int kChunk)
{
    extern __shared__ __align__(16) char sm[];
    const uint32_t smb = smem_u32(sm);

    const int tid = threadIdx.x;
    const int wid = tid >> 5;
    const int lane = tid & 31;
    const int warp_m = wid & 3;
    const int warp_n = wid >> 2;

    const int m0 = blockIdx.y * 128;
    const int n0 = blockIdx.x * 128;
    const int kBeg = blockIdx.z * kChunk;
    const int nkt = kChunk >> 5;
    float* Cout = C + (size_t)blockIdx.z * (size_t)M * (size_t)N;

    float acc[2][8][4];
#pragma unroll
    for (int mt = 0; mt < 2; mt++)
#pragma unroll
        for (int nf = 0; nf < 8; nf++)
#pragma unroll
            for (int e = 0; e < 4; e++) acc[mt][nf][e] = 0.f;

    const int lr = tid >> 3;
    const int c4 = tid & 7;
    const float* Ab = A + (size_t)(m0 + lr) * (size_t)K + c4 * 4;
    const float* Bb = BT + (size_t)(n0 + lr) * (size_t)K + c4 * 4;
    const uint32_t stoff = (uint32_t)(lr * PITCH + c4 * 8);

    const uint32_t a_row = (uint32_t)(warp_m * 32 + (lane & 15));
    const uint32_t a_off = a_row * PITCH + ((uint32_t)(lane >> 4) << 4);
    const uint32_t b_row = (uint32_t)(warp_n * 64 + (lane & 7) + ((lane >> 4) << 3));
    const uint32_t b_off = b_row * PITCH + (((uint32_t)(lane >> 3) & 1) << 4);

    for (int kt = 0; kt < nkt; kt++) MAINLOOP_TILE();

    const int erow = m0 + warp_m * 32 + (lane >> 2);
    const int ecol = n0 + warp_n * 64 + 2 * (lane & 3);
#pragma unroll
    for (int mt = 0; mt < 2; mt++) {
#pragma unroll
        for (int nf = 0; nf < 8; nf++) {
            float* p0 = Cout + (size_t)(erow + mt * 16) * (size_t)N + ecol + nf * 8;
            float* p1 = p0 + (size_t)8 * (size_t)N;
            *(float2*)p0 = make_float2(acc[mt][nf][0], acc[mt][nf][1]);
            *(float2*)p1 = make_float2(acc[mt][nf][2], acc[mt][nf][3]);
        }
    }
}

// ---------------------------------------------------------------------------
// Symmetric rank-k: C = Z @ Z^T, Z = [NN, DZ]. Upper-triangle CTAs (bj>=bi)
// compute; off-diagonal tiles are transposed through smem and mirror-written
// coalesced. The 3-term compensation formula is exactly symmetric, so the
// mirror is numerically identical to recomputation.
// ---------------------------------------------------------------------------
__global__ void __launch_bounds__(256, 2)
bf16x3_syrk(const float* __restrict__ Z, float* __restrict__ C)
{
    const int bi = blockIdx.y, bj = blockIdx.x;
    if (bj < bi) return;

    extern __shared__ __align__(16) char sm[];
    const uint32_t smb = smem_u32(sm);

    const int tid = threadIdx.x;
    const int wid = tid >> 5;
    const int lane = tid & 31;
    const int warp_m = wid & 3;
    const int warp_n = wid >> 2;

    const int m0 = bi * 128;
    const int n0 = bj * 128;
    const int K = DZ;
    const int kBeg = 0;
    const int nkt = DZ >> 5;          // 2

    float acc[2][8][4];
#pragma unroll
    for (int mt = 0; mt < 2; mt++)
#pragma unroll
        for (int nf = 0; nf < 8; nf++)
#pragma unroll
            for (int e = 0; e < 4; e++) acc[mt][nf][e] = 0.f;

    const int lr = tid >> 3;
    const int c4 = tid & 7;
    const float* Ab = Z + (size_t)(m0 + lr) * (size_t)K + c4 * 4;
    const float* Bb = Z + (size_t)(n0 + lr) * (size_t)K + c4 * 4;
    const uint32_t stoff = (uint32_t)(lr * PITCH + c4 * 8);

    const uint32_t a_row = (uint32_t)(warp_m * 32 + (lane & 15));
    const uint32_t a_off = a_row * PITCH + ((uint32_t)(lane >> 4) << 4);
    const uint32_t b_row = (uint32_t)(warp_n * 64 + (lane & 7) + ((lane >> 4) << 3));
    const uint32_t b_off = b_row * PITCH + (((uint32_t)(lane >> 3) & 1) << 4);

    for (int kt = 0; kt < nkt; kt++) MAINLOOP_TILE();

    // own tile (coalesced)
    const int erow0 = warp_m * 32 + (lane >> 2);
    const int ecol0 = warp_n * 64 + 2 * (lane & 3);
#pragma unroll
    for (int mt = 0; mt < 2; mt++) {
#pragma unroll
        for (int nf = 0; nf < 8; nf++) {
            float* p0 = C + (size_t)(m0 + erow0 + mt * 16) * (size_t)NN
                          + n0 + ecol0 + nf * 8;
            float* p1 = p0 + (size_t)8 * (size_t)NN;
            *(float2*)p0 = make_float2(acc[mt][nf][0], acc[mt][nf][1]);
            *(float2*)p1 = make_float2(acc[mt][nf][2], acc[mt][nf][3]);
        }
    }

    // mirror tile via smem transpose (coalesced writes)
    if (bi != bj) {
        __syncthreads();                       // stage smem no longer needed
        float* smT = (float*)sm;               // [128][128] pitch 132 floats
#pragma unroll
        for (int mt = 0; mt < 2; mt++)
#pragma unroll
            for (int nf = 0; nf < 8; nf++) {
                const int rr = erow0 + mt * 16;
                const int cc = ecol0 + nf * 8;
                smT[(cc + 0) * 132 + rr]     = acc[mt][nf][0];
                smT[(cc + 1) * 132 + rr]     = acc[mt][nf][1];
                smT[(cc + 0) * 132 + rr + 8] = acc[mt][nf][2];
                smT[(cc + 1) * 132 + rr + 8] = acc[mt][nf][3];
            }
        __syncthreads();
        const int r2 = tid >> 1;               // mirror row (original col)
        const int half = (tid & 1) * 64;
        float* dst = C + (size_t)(n0 + r2) * (size_t)NN + m0 + half;
        const float* src = smT + r2 * 132 + half;
#pragma unroll
        for (int j = 0; j < 16; j++)
            *(float4*)(dst + j * 4) = *(const float4*)(src + j * 4);
    }
}

// ---------------------------------------------------------------------------
// helpers: transpose, pack, reduces
// ---------------------------------------------------------------------------
__global__ void transpose_k(const float* __restrict__ in, float* __restrict__ out,
                            int R, int C) {
    __shared__ float t[32][33];
    const int c0 = blockIdx.x * 32, r0 = blockIdx.y * 32;
    const int tx = threadIdx.x, ty = threadIdx.y;
#pragma unroll
    for (int j = 0; j < 4; j++)
        t[ty + j * 8][tx] = in[(size_t)(r0 + ty + j * 8) * (size_t)C + c0 + tx];
    __syncthreads();
#pragma unroll
    for (int j = 0; j < 4; j++)
        out[(size_t)(c0 + ty + j * 8) * (size_t)R + r0 + tx] = t[tx][ty + j * 8];
}

// WcT[c][r] = c<64 ? Wm[r][c] : Wl[r][c-64];  WcT is [128,256]
__global__ void pack_wct(const float* __restrict__ Wm, const float* __restrict__ Wl,
                         float* __restrict__ WcT) {
    int i = blockIdx.x * blockDim.x + threadIdx.x;    // 128*256
    if (i >= DCAT * DHID) return;
    int c = i >> 8, r = i & 255;
    WcT[i] = (c < DZ) ? Wm[r * DZ + c] : Wl[r * DZ + (c - DZ)];
}

template<int S, bool RELU>
__global__ void reduceN(const float* __restrict__ p, size_t stride,
                        float* __restrict__ out, int n4) {
    int i = blockIdx.x * blockDim.x + threadIdx.x;
    if (i >= n4) return;
    float4 r = ((const float4*)p)[i];
#pragma unroll
    for (int s = 1; s < S; s++) {
        float4 v = ((const float4*)(p + (size_t)s * stride))[i];
        r.x += v.x; r.y += v.y; r.z += v.z; r.w += v.w;
    }
    if (RELU) {
        r.x = fmaxf(r.x, 0.f); r.y = fmaxf(r.y, 0.f);
        r.z = fmaxf(r.z, 0.f); r.w = fmaxf(r.w, 0.f);
    }
    ((float4*)out)[i] = r;
}

// zcat = sum of 16 slices; split cols [0,64)->zm, [64,128)->zl
__global__ void reduce16_split(const float* __restrict__ p, size_t stride,
                               float* __restrict__ zm, float* __restrict__ zl) {
    int i = blockIdx.x * blockDim.x + threadIdx.x;    // NN*DCAT/4
    if (i >= NN * DCAT / 4) return;
    int row = i >> 5, c4 = i & 31;
    float4 r = ((const float4*)p)[i];
#pragma unroll
    for (int s = 1; s < 16; s++) {
        float4 v = ((const float4*)(p + (size_t)s * stride))[i];
        r.x += v.x; r.y += v.y; r.z += v.z; r.w += v.w;
    }
    if (c4 < 16) ((float4*)zm)[(size_t)row * 16 + c4] = r;
    else         ((float4*)zl)[(size_t)row * 16 + (c4 - 16)] = r;
}

// ---------------------------------------------------------------------------
extern "C" void kernel_launch(void* const* d_in, const int* in_sizes, int n_in,
                              void* d_out, int out_size) {
    const float* x = nullptr;
    const float* adj = nullptr;
    const float* Wh = nullptr;
    const float* Wsmall[2] = {nullptr, nullptr};
    int nsmall = 0;
    for (int i = 0; i < n_in; i++) {
        const float* p = (const float*)d_in[i];
        switch (in_sizes[i]) {
            case NN * DIN:   x = p; break;
            case NN * NN:    adj = p; break;
            case DIN * DHID: Wh = p; break;
            case DHID * DZ:  if (nsmall < 2) Wsmall[nsmall++] = p; break;
            default: break;
        }
    }
    const float* Wm = Wsmall[0];
    const float* Wl = Wsmall[1];

    float* out = (float*)d_out;
    float* recon = out;
    float* zm = out + (size_t)NN * (size_t)NN;
    float* zl = zm + (size_t)NN * (size_t)DZ;

    float* ws = nullptr;
    cudaGetSymbolAddress((void**)&ws, g_scratch);
    float* support = ws + OFF_SUPPORT;
    float* supT    = ws + OFF_SUPT;
    float* hidden  = ws + OFF_HIDDEN;
    float* part    = ws + OFF_PART;
    float* sbuf    = ws + OFF_S;
    float* sT      = ws + OFF_ST;
    float* WhT     = ws + OFF_WHT;
    float* WcT     = ws + OFF_WCT;

    cudaFuncSetAttribute(bf16x3_gemm, cudaFuncAttributeMaxDynamicSharedMemorySize,
                         GEMM_SMEM);
    cudaFuncSetAttribute(bf16x3_syrk, cudaFuncAttributeMaxDynamicSharedMemorySize,
                         GEMM_SMEM);

    // weights -> K-major
    transpose_k<<<dim3(DHID / 32, DIN / 32), dim3(32, 8)>>>(Wh, WhT, DIN, DHID);
    pack_wct<<<(DCAT * DHID + 255) / 256, 256>>>(Wm, Wl, WcT);

    // support = x @ Wh, split-K 2 (256 CTAs)
    bf16x3_gemm<<<dim3(2, 64, 2), 256, GEMM_SMEM>>>(x, WhT, part, NN, DHID, DIN, DIN / 2);
    reduceN<2, false><<<(NN * DHID / 4 + 255) / 256, 256>>>(part, (size_t)NN * DHID,
                                                            support, NN * DHID / 4);
    transpose_k<<<dim3(DHID / 32, NN / 32), dim3(32, 8)>>>(support, supT, NN, DHID);

    // hidden = relu(adj @ support), split-K 8 (1024 CTAs -> ~7/SM balanced)
    bf16x3_gemm<<<dim3(2, 64, 8), 256, GEMM_SMEM>>>(adj, supT, part, NN, DHID, NN, NN / 8);
    reduceN<8, true><<<(NN * DHID / 4 + 255) / 256, 256>>>(part, (size_t)NN * DHID,
                                                           hidden, NN * DHID / 4);

    // s = hidden @ [Wm|Wl], split-K 4 (256 CTAs)
    bf16x3_gemm<<<dim3(1, 64, 4), 256, GEMM_SMEM>>>(hidden, WcT, part, NN, DCAT, DHID,
                                                    DHID / 4);
    reduceN<4, false><<<(NN * DCAT / 4 + 255) / 256, 256>>>(part, (size_t)NN * DCAT,
                                                            sbuf, NN * DCAT / 4);
    transpose_k<<<dim3(DCAT / 32, NN / 32), dim3(32, 8)>>>(sbuf, sT, NN, DCAT);

    // zcat = adj @ s, split-K 16 (1024 CTAs) -> z_mean, z_log_std
    bf16x3_gemm<<<dim3(1, 64, 16), 256, GEMM_SMEM>>>(adj, sT, part, NN, DCAT, NN, NN / 16);
    reduce16_split<<<(NN * DCAT / 4 + 255) / 256, 256>>>(part, (size_t)NN * DCAT, zm, zl);

    // recon = z_mean @ z_mean^T (symmetric; upper-triangle CTAs only)
    bf16x3_syrk<<<dim3(64, 64), 256, GEMM_SMEM>>>(zm, recon);
}

// round 12
// speedup vs baseline: 2.7239x; 1.0156x over previous
#include <cuda_runtime.h>
#include <cuda_bf16.h>
#include <cstdint>

// ---------------------------------------------------------------------------
// GCNModelVAE forward — bf16 mma.sync GEMMs with 3-term error compensation.
// (tcgen05 unavailable: harness ptxas targets plain sm_103)
//   support = x @ Wh                  [8192,512]@[512,256]    split-K 2
//   hidden  = relu(adj @ support)     [8192,8192]@[8192,256]  split-K 8
//   s       = hidden @ [Wm|Wl]        [8192,256]@[256,128]    split-K 4
//   zcat    = adj @ s                 [8192,8192]@[8192,128]  split-K 16
//   recon   = z_mean @ z_mean^T       [8192,64] symmetric rank-k (upper CTAs)
// Output: [recon | z_mean | z_log_std]
//
// Compensation: a = ah + al (bf16 hi + bf16 residual);
//   C = Ah*Bl + Al*Bh + Ah*Bh   (Al*Bl ~2^-18 dropped) -> ~1e-5 per GEMM.
// R12 changes: B operand consumed in natural [K,N] layout via ldmatrix.trans
// (kills both transpose_k passes + their traffic); reducers do 4 float4/thread
// (they were latency-bound at 2.4 TB/s). syrk keeps the K-major path.
// ---------------------------------------------------------------------------

#define NN   8192
#define DIN  512
#define DHID 256
#define DZ   64
#define DCAT 128

// ---- scratch (allocation-free) ----
#define SZ_PART     (16*NN*DCAT)
#define OFF_SUPPORT 0
#define OFF_HIDDEN  (OFF_SUPPORT + NN*DHID)
#define OFF_PART    (OFF_HIDDEN  + NN*DHID)
#define OFF_S       (OFF_PART    + SZ_PART)
#define OFF_WCAT    (OFF_S       + NN*DCAT)
#define SZ_TOTAL    (OFF_WCAT    + DHID*DCAT)

__device__ __align__(16) float g_scratch[SZ_TOTAL];

// ---------------------------------------------------------------------------
// helpers
// ---------------------------------------------------------------------------
__device__ __forceinline__ uint32_t smem_u32(const void* p) {
    uint32_t a;
    asm("{ .reg .u64 t; cvta.to.shared.u64 t, %1; cvt.u32.u64 %0, t; }"
        : "=r"(a) : "l"(p));
    return a;
}

__device__ __forceinline__ uint32_t pack_bf2(float lo, float hi) {
    uint32_t r;
    asm("cvt.rn.bf16x2.f32 %0, %1, %2;" : "=r"(r) : "f"(hi), "f"(lo));
    return r;
}

__device__ __forceinline__ void ldm_x4(uint32_t* r, uint32_t addr) {
    asm volatile("ldmatrix.sync.aligned.m8n8.x4.shared.b16 {%0,%1,%2,%3}, [%4];"
                 : "=r"(r[0]), "=r"(r[1]), "=r"(r[2]), "=r"(r[3]) : "r"(addr));
}

__device__ __forceinline__ void ldm_x4_t(uint32_t* r, uint32_t addr) {
    asm volatile("ldmatrix.sync.aligned.m8n8.x4.trans.shared.b16 {%0,%1,%2,%3}, [%4];"
                 : "=r"(r[0]), "=r"(r[1]), "=r"(r[2]), "=r"(r[3]) : "r"(addr));
}

__device__ __forceinline__ void mma_bf16(float* c, const uint32_t* a, const uint32_t* b) {
    asm volatile(
        "mma.sync.aligned.m16n8k16.row.col.f32.bf16.bf16.f32 "
        "{%0,%1,%2,%3}, {%4,%5,%6,%7}, {%8,%9}, {%0,%1,%2,%3};"
        : "+f"(c[0]), "+f"(c[1]), "+f"(c[2]), "+f"(c[3])
        : "r"(a[0]), "r"(a[1]), "r"(a[2]), "r"(a[3]), "r"(b[0]), "r"(b[1]));
}

__device__ __forceinline__ void split_pack(float4 v, uint2& hp, uint2& lp) {
    hp.x = pack_bf2(v.x, v.y);
    hp.y = pack_bf2(v.z, v.w);
    float h0 = __uint_as_float(hp.x << 16);
    float h1 = __uint_as_float(hp.x & 0xffff0000u);
    float h2 = __uint_as_float(hp.y << 16);
    float h3 = __uint_as_float(hp.y & 0xffff0000u);
    lp.x = pack_bf2(v.x - h0, v.y - h1);
    lp.y = pack_bf2(v.z - h2, v.w - h3);
}

// ---------------------------------------------------------------------------
// smem layouts
// ---------------------------------------------------------------------------
#define PITCH   80                  // A tiles: [row m][64B of k], 80B pitch
#define SEGSZ   (128 * PITCH)       // 10240
// B (nmajor kernel): [row k][256B of n], pitch 272 (68 words: ldmatrix-phase
// conflict-free: 8 lanes at stride 68w, 16B each -> all 32 banks once)
#define PITCHB  272
#define SEGB    (32 * PITCHB)       // 8704

// nmajor stage layout
#define N_AH    0
#define N_AL    (1 * SEGSZ)
#define N_BH    (2 * SEGSZ)
#define N_BL    (2 * SEGSZ + SEGB)
#define N_STAGE (2 * SEGSZ + 2 * SEGB)   // 37888
#define N_SMEM  (2 * N_STAGE)            // 75776

// kmajor (syrk) stage layout — unchanged from R11
#define SEG_AH  0
#define SEG_AL  (1 * SEGSZ)
#define SEG_BL  (2 * SEGSZ)
#define SEG_BH  (3 * SEGSZ)
#define GSTAGE  (4 * SEGSZ)              // 40960
#define K_SMEM  (2 * GSTAGE)             // 81920

// ---------------------------------------------------------------------------
// bf16x3 GEMM, B in natural [K,N] row-major (ldB): C = A[M,K] @ B[K,N].
// BM=BN=128, BK=32. 256 threads, warps 4(m) x 2(n), warp tile 32x64.
// 2 smem stages, ONE __syncthreads per k-tile; occupancy 2.
// grid=(N/128, M/128, K/kChunk); slice z writes C + z*M*N.
// ---------------------------------------------------------------------------
__global__ void __launch_bounds__(256, 2)
bf16x3_gemm_bn(const float* __restrict__ A, const float* __restrict__ B,
               float* __restrict__ C, int M, int N, int K, int ldB, int kChunk)
{
    extern __shared__ __align__(16) char sm[];
    const uint32_t smb = smem_u32(sm);

    const int tid = threadIdx.x;
    const int wid = tid >> 5;
    const int lane = tid & 31;
    const int warp_m = wid & 3;
    const int warp_n = wid >> 2;

    const int m0 = blockIdx.y * 128;
    const int n0 = blockIdx.x * 128;
    const int kBeg = blockIdx.z * kChunk;
    const int nkt = kChunk >> 5;
    float* Cout = C + (size_t)blockIdx.z * (size_t)M * (size_t)N;

    float acc[2][8][4];
#pragma unroll
    for (int mt = 0; mt < 2; mt++)
#pragma unroll
        for (int nf = 0; nf < 8; nf++)
#pragma unroll
            for (int e = 0; e < 4; e++) acc[mt][nf][e] = 0.f;

    // A loader: thread -> (row = lr + 32i, k-float4 = c4)
    const int lr = tid >> 3;
    const int c4 = tid & 7;
    const float* Ab = A + (size_t)(m0 + lr) * (size_t)K + c4 * 4;
    const uint32_t stA = (uint32_t)(lr * PITCH + c4 * 8);

    // B loader: thread -> (k-row = kq, n-float4 = ncb + 8i)
    const int kq = tid >> 3;          // 0..31
    const int ncb = tid & 7;
    const float* Bb = B + (size_t)kq * (size_t)ldB + n0 + ncb * 4;
    const uint32_t stB = (uint32_t)(kq * PITCHB + ncb * 8);

    // A fragment addresses (kmajor, unchanged)
    const uint32_t a_row = (uint32_t)(warp_m * 32 + (lane & 15));
    const uint32_t a_off = a_row * PITCH + ((uint32_t)(lane >> 4) << 4);
    // B fragment addresses for ldmatrix.trans from [k][n] layout:
    // lanes 0-7 -> k rows 0-7 @ n+0 ; 8-15 -> k 8-15 @ n+0 ;
    // lanes 16-23 -> k 0-7 @ n+8 ; 24-31 -> k 8-15 @ n+8.
    const uint32_t b_row = (uint32_t)((lane & 7) + ((lane >> 3) & 1) * 8);
    const uint32_t b_off = b_row * PITCHB + (uint32_t)warp_n * 128u
                         + (((uint32_t)lane >> 4) << 4);

    for (int kt = 0; kt < nkt; kt++) {
        const uint32_t stg = (uint32_t)(kt & 1) * N_STAGE;
        char* sp = sm + stg;
        const int k0 = kBeg + (kt << 5);

        // ---- load + convert + store tiles ----
#pragma unroll
        for (int i = 0; i < 4; i++) {
            const uint32_t offA = stA + (uint32_t)(i * 32 * PITCH);
            float4 va = *(const float4*)(Ab + (size_t)(i * 32) * (size_t)K + k0);
            uint2 hp, lp;
            split_pack(va, hp, lp);
            *(uint2*)(sp + N_AH + offA) = hp;
            *(uint2*)(sp + N_AL + offA) = lp;
            float4 vb = *(const float4*)(Bb + (size_t)k0 * (size_t)ldB + i * 32);
            split_pack(vb, hp, lp);
            const uint32_t offB = stB + (uint32_t)(i * 64);
            *(uint2*)(sp + N_BH + offB) = hp;
            *(uint2*)(sp + N_BL + offB) = lp;
        }
        __syncthreads();

        // ---- compute: 2 k16 steps x 3 compensation passes ----
        const uint32_t sa = smb + stg + a_off;
        const uint32_t sb = smb + stg + b_off;
#pragma unroll
        for (int kk = 0; kk < 2; kk++) {
            const uint32_t kbA = (uint32_t)(kk * 32);
            const uint32_t kbB = (uint32_t)(kk * 16 * PITCHB);
            uint32_t Ah[2][4], Al[2][4];
#pragma unroll
            for (int mt = 0; mt < 2; mt++) {
                const uint32_t base = sa + (uint32_t)(mt * 16 * PITCH) + kbA;
                ldm_x4(Ah[mt], base + N_AH);
                ldm_x4(Al[mt], base + N_AL);
            }
            uint32_t Bf[8][2];
            // pass 0: Ah * Bl
#pragma unroll
            for (int nf2 = 0; nf2 < 4; nf2++) {
                uint32_t t[4];
                ldm_x4_t(t, sb + N_BL + (uint32_t)(nf2 * 32) + kbB);
                Bf[2 * nf2][0] = t[0]; Bf[2 * nf2][1] = t[1];
                Bf[2 * nf2 + 1][0] = t[2]; Bf[2 * nf2 + 1][1] = t[3];
            }
#pragma unroll
            for (int mt = 0; mt < 2; mt++)
#pragma unroll
                for (int nf = 0; nf < 8; nf++)
                    mma_bf16(acc[mt][nf], Ah[mt], Bf[nf]);
            // passes 1+2: Al * Bh, Ah * Bh
#pragma unroll
            for (int nf2 = 0; nf2 < 4; nf2++) {
                uint32_t t[4];
                ldm_x4_t(t, sb + N_BH + (uint32_t)(nf2 * 32) + kbB);
                Bf[2 * nf2][0] = t[0]; Bf[2 * nf2][1] = t[1];
                Bf[2 * nf2 + 1][0] = t[2]; Bf[2 * nf2 + 1][1] = t[3];
            }
#pragma unroll
            for (int mt = 0; mt < 2; mt++)
#pragma unroll
                for (int nf = 0; nf < 8; nf++) {
                    mma_bf16(acc[mt][nf], Al[mt], Bf[nf]);
                    mma_bf16(acc[mt][nf], Ah[mt], Bf[nf]);
                }
        }
    }

    const int erow = m0 + warp_m * 32 + (lane >> 2);
    const int ecol = n0 + warp_n * 64 + 2 * (lane & 3);
#pragma unroll
    for (int mt = 0; mt < 2; mt++) {
#pragma unroll
        for (int nf = 0; nf < 8; nf++) {
            float* p0 = Cout + (size_t)(erow + mt * 16) * (size_t)N + ecol + nf * 8;
            float* p1 = p0 + (size_t)8 * (size_t)N;
            *(float2*)p0 = make_float2(acc[mt][nf][0], acc[mt][nf][1]);
            *(float2*)p1 = make_float2(acc[mt][nf][2], acc[mt][nf][3]);
        }
    }
}

// ---------------------------------------------------------------------------
// Symmetric rank-k (K-major B path, unchanged from R11): C = Z @ Z^T.
// Upper-triangle CTAs compute; mirror tiles transposed via smem, coalesced.
// ---------------------------------------------------------------------------
__global__ void __launch_bounds__(256, 2)
bf16x3_syrk(const float* __restrict__ Z, float* __restrict__ C)
{
    const int bi = blockIdx.y, bj = blockIdx.x;
    if (bj < bi) return;

    extern __shared__ __align__(16) char sm[];
    const uint32_t smb = smem_u32(sm);

    const int tid = threadIdx.x;
    const int wid = tid >> 5;
    const int lane = tid & 31;
    const int warp_m = wid & 3;
    const int warp_n = wid >> 2;

    const int m0 = bi * 128;
    const int n0 = bj * 128;
    const int K = DZ;

    float acc[2][8][4];
#pragma unroll
    for (int mt = 0; mt < 2; mt++)
#pragma unroll
        for (int nf = 0; nf < 8; nf++)
#pragma unroll
            for (int e = 0; e < 4; e++) acc[mt][nf][e] = 0.f;

    const int lr = tid >> 3;
    const int c4 = tid & 7;
    const float* Ab = Z + (size_t)(m0 + lr) * (size_t)K + c4 * 4;
    const float* Bb = Z + (size_t)(n0 + lr) * (size_t)K + c4 * 4;
    const uint32_t stoff = (uint32_t)(lr * PITCH + c4 * 8);

    const uint32_t a_row = (uint32_t)(warp_m * 32 + (lane & 15));
    const uint32_t a_off = a_row * PITCH + ((uint32_t)(lane >> 4) << 4);
    const uint32_t b_row = (uint32_t)(warp_n * 64 + (lane & 7) + ((lane >> 4) << 3));
    const uint32_t b_off = b_row * PITCH + (((uint32_t)(lane >> 3) & 1) << 4);

    for (int kt = 0; kt < 2; kt++) {
        const uint32_t stg = (uint32_t)(kt & 1) * GSTAGE;
        char* sp = sm + stg;
        const int k0 = kt << 5;
#pragma unroll
        for (int i = 0; i < 4; i++) {
            const uint32_t off = stoff + (uint32_t)(i * 32 * PITCH);
            float4 va = *(const float4*)(Ab + (size_t)(i * 32) * (size_t)K + k0);
            float4 vb = *(const float4*)(Bb + (size_t)(i * 32) * (size_t)K + k0);
            uint2 hp, lp;
            split_pack(va, hp, lp);
            *(uint2*)(sp + SEG_AH + off) = hp;
            *(uint2*)(sp + SEG_AL + off) = lp;
            split_pack(vb, hp, lp);
            *(uint2*)(sp + SEG_BH + off) = hp;
            *(uint2*)(sp + SEG_BL + off) = lp;
        }
        __syncthreads();
        const uint32_t sa = smb + stg + a_off;
        const uint32_t sb = smb + stg + b_off;
#pragma unroll
        for (int kk = 0; kk < 2; kk++) {
            const uint32_t kb = (uint32_t)(kk * 32);
            uint32_t Ah[2][4], Al[2][4];
#pragma unroll
            for (int mt = 0; mt < 2; mt++) {
                const uint32_t base = sa + (uint32_t)(mt * 16 * PITCH) + kb;
                ldm_x4(Ah[mt], base + SEG_AH);
                ldm_x4(Al[mt], base + SEG_AL);
            }
            uint32_t Bf[8][2];
#pragma unroll
            for (int nf2 = 0; nf2 < 4; nf2++) {
                uint32_t t[4];
                ldm_x4(t, sb + SEG_BL + (uint32_t)(nf2 * 16 * PITCH) + kb);
                Bf[2 * nf2][0] = t[0]; Bf[2 * nf2][1] = t[1];
                Bf[2 * nf2 + 1][0] = t[2]; Bf[2 * nf2 + 1][1] = t[3];
            }
#pragma unroll
            for (int mt = 0; mt < 2; mt++)
#pragma unroll
                for (int nf = 0; nf < 8; nf++)
                    mma_bf16(acc[mt][nf], Ah[mt], Bf[nf]);
#pragma unroll
            for (int nf2 = 0; nf2 < 4; nf2++) {
                uint32_t t[4];
                ldm_x4(t, sb + SEG_BH + (uint32_t)(nf2 * 16 * PITCH) + kb);
                Bf[2 * nf2][0] = t[0]; Bf[2 * nf2][1] = t[1];
                Bf[2 * nf2 + 1][0] = t[2]; Bf[2 * nf2 + 1][1] = t[3];
            }
#pragma unroll
            for (int mt = 0; mt < 2; mt++)
#pragma unroll
                for (int nf = 0; nf < 8; nf++) {
                    mma_bf16(acc[mt][nf], Al[mt], Bf[nf]);
                    mma_bf16(acc[mt][nf], Ah[mt], Bf[nf]);
                }
        }
    }

    const int erow0 = warp_m * 32 + (lane >> 2);
    const int ecol0 = warp_n * 64 + 2 * (lane & 3);
#pragma unroll
    for (int mt = 0; mt < 2; mt++) {
#pragma unroll
        for (int nf = 0; nf < 8; nf++) {
            float* p0 = C + (size_t)(m0 + erow0 + mt * 16) * (size_t)NN
                          + n0 + ecol0 + nf * 8;
            float* p1 = p0 + (size_t)8 * (size_t)NN;
            *(float2*)p0 = make_float2(acc[mt][nf][0], acc[mt][nf][1]);
            *(float2*)p1 = make_float2(acc[mt][nf][2], acc[mt][nf][3]);
        }
    }

    if (bi != bj) {
        __syncthreads();
        float* smT = (float*)sm;               // [128][132]
#pragma unroll
        for (int mt = 0; mt < 2; mt++)
#pragma unroll
            for (int nf = 0; nf < 8; nf++) {
                const int rr = erow0 + mt * 16;
                const int cc = ecol0 + nf * 8;
                smT[(cc + 0) * 132 + rr]     = acc[mt][nf][0];
                smT[(cc + 1) * 132 + rr]     = acc[mt][nf][1];
                smT[(cc + 0) * 132 + rr + 8] = acc[mt][nf][2];
                smT[(cc + 1) * 132 + rr + 8] = acc[mt][nf][3];
            }
        __syncthreads();
        const int r2 = tid >> 1;
        const int half = (tid & 1) * 64;
        float* dst = C + (size_t)(n0 + r2) * (size_t)NN + m0 + half;
        const float* src = smT + r2 * 132 + half;
#pragma unroll
        for (int j = 0; j < 16; j++)
            *(float4*)(dst + j * 4) = *(const float4*)(src + j * 4);
    }
}

// ---------------------------------------------------------------------------
// helpers: pack, reducers (4 float4 per thread)
// ---------------------------------------------------------------------------
// Wcat[k][c] = c<64 ? Wm[k][c] : Wl[k][c-64];  Wcat is [256,128] (natural K,N)
__global__ void pack_wcat(const float* __restrict__ Wm, const float* __restrict__ Wl,
                          float* __restrict__ Wcat) {
    int i = blockIdx.x * blockDim.x + threadIdx.x;    // 256*128
    if (i >= DHID * DCAT) return;
    int k = i >> 7, c = i & 127;
    Wcat[i] = (c < DZ) ? Wm[k * DZ + c] : Wl[k * DZ + (c - DZ)];
}

template<int S, bool RELU>
__global__ void reduceN(const float* __restrict__ p, size_t stride,
                        float* __restrict__ out, int n4) {
    int base = blockIdx.x * (blockDim.x * 4) + threadIdx.x;
#pragma unroll
    for (int j = 0; j < 4; j++) {
        int i = base + j * 256;
        if (i >= n4) return;
        float4 r = ((const float4*)p)[i];
#pragma unroll
        for (int s = 1; s < S; s++) {
            float4 v = ((const float4*)(p + (size_t)s * stride))[i];
            r.x += v.x; r.y += v.y; r.z += v.z; r.w += v.w;
        }
        if (RELU) {
            r.x = fmaxf(r.x, 0.f); r.y = fmaxf(r.y, 0.f);
            r.z = fmaxf(r.z, 0.f); r.w = fmaxf(r.w, 0.f);
        }
        ((float4*)out)[i] = r;
    }
}

__global__ void reduce16_split(const float* __restrict__ p, size_t stride,
                               float* __restrict__ zm, float* __restrict__ zl) {
    int base = blockIdx.x * (blockDim.x * 4) + threadIdx.x;
#pragma unroll
    for (int j = 0; j < 4; j++) {
        int i = base + j * 256;
        if (i >= NN * DCAT / 4) return;
        int row = i >> 5, c4 = i & 31;
        float4 r = ((const float4*)p)[i];
#pragma unroll
        for (int s = 1; s < 16; s++) {
            float4 v = ((const float4*)(p + (size_t)s * stride))[i];
            r.x += v.x; r.y += v.y; r.z += v.z; r.w += v.w;
        }
        if (c4 < 16) ((float4*)zm)[(size_t)row * 16 + c4] = r;
        else         ((float4*)zl)[(size_t)row * 16 + (c4 - 16)] = r;
    }
}

// ---------------------------------------------------------------------------
extern "C" void kernel_launch(void* const* d_in, const int* in_sizes, int n_in,
                              void* d_out, int out_size) {
    const float* x = nullptr;
    const float* adj = nullptr;
    const float* Wh = nullptr;
    const float* Wsmall[2] = {nullptr, nullptr};
    int nsmall = 0;
    for (int i = 0; i < n_in; i++) {
        const float* p = (const float*)d_in[i];
        switch (in_sizes[i]) {
            case NN * DIN:   x = p; break;
            case NN * NN:    adj = p; break;
            case DIN * DHID: Wh = p; break;
            case DHID * DZ:  if (nsmall < 2) Wsmall[nsmall++] = p; break;
            default: break;
        }
    }
    const float* Wm = Wsmall[0];
    const float* Wl = Wsmall[1];

    float* out = (float*)d_out;
    float* recon = out;
    float* zm = out + (size_t)NN * (size_t)NN;
    float* zl = zm + (size_t)NN * (size_t)DZ;

    float* ws = nullptr;
    cudaGetSymbolAddress((void**)&ws, g_scratch);
    float* support = ws + OFF_SUPPORT;
    float* hidden  = ws + OFF_HIDDEN;
    float* part    = ws + OFF_PART;
    float* sbuf    = ws + OFF_S;
    float* wcat    = ws + OFF_WCAT;

    cudaFuncSetAttribute(bf16x3_gemm_bn, cudaFuncAttributeMaxDynamicSharedMemorySize,
                         N_SMEM);
    cudaFuncSetAttribute(bf16x3_syrk, cudaFuncAttributeMaxDynamicSharedMemorySize,
                         K_SMEM);

    pack_wcat<<<(DHID * DCAT + 255) / 256, 256>>>(Wm, Wl, wcat);

    // support = x @ Wh, split-K 2
    bf16x3_gemm_bn<<<dim3(2, 64, 2), 256, N_SMEM>>>(x, Wh, part, NN, DHID, DIN,
                                                    DHID, DIN / 2);
    reduceN<2, false><<<(NN * DHID / 4 + 1023) / 1024, 256>>>(part, (size_t)NN * DHID,
                                                              support, NN * DHID / 4);

    // hidden = relu(adj @ support), split-K 8
    bf16x3_gemm_bn<<<dim3(2, 64, 8), 256, N_SMEM>>>(adj, support, part, NN, DHID, NN,
                                                    DHID, NN / 8);
    reduceN<8, true><<<(NN * DHID / 4 + 1023) / 1024, 256>>>(part, (size_t)NN * DHID,
                                                             hidden, NN * DHID / 4);

    // s = hidden @ [Wm|Wl], split-K 4
    bf16x3_gemm_bn<<<dim3(1, 64, 4), 256, N_SMEM>>>(hidden, wcat, part, NN, DCAT, DHID,
                                                    DCAT, DHID / 4);
    reduceN<4, false><<<(NN * DCAT / 4 + 1023) / 1024, 256>>>(part, (size_t)NN * DCAT,
                                                              sbuf, NN * DCAT / 4);

    // zcat = adj @ s, split-K 16 -> z_mean, z_log_std
    bf16x3_gemm_bn<<<dim3(1, 64, 16), 256, N_SMEM>>>(adj, sbuf, part, NN, DCAT, NN,
                                                     DCAT, NN / 16);
    reduce16_split<<<(NN * DCAT / 4 + 1023) / 1024, 256>>>(part, (size_t)NN * DCAT,
                                                           zm, zl);

    // recon = z_mean @ z_mean^T (symmetric)
    bf16x3_syrk<<<dim3(64, 64), 256, K_SMEM>>>(zm, recon);
}

// round 13
// speedup vs baseline: 2.8387x; 1.0421x over previous
#include <cuda_runtime.h>
#include <cuda_bf16.h>
#include <cstdint>

// ---------------------------------------------------------------------------
// GCNModelVAE forward — bf16 mma.sync GEMMs with 3-term error compensation.
// (tcgen05 unavailable: harness ptxas targets plain sm_103)
//   support = x @ Wh                  [8192,512]@[512,256]    split-K 2
//   hidden  = relu(adj @ support)     [8192,8192]@[8192,256]  split-K 8
//   s       = hidden @ [Wm|Wl]        [8192,256]@[256,128]    split-K 4
//   zcat    = adj @ s                 [8192,8192]@[8192,128]  split-K 16
//   recon   = z_mean @ z_mean^T       [8192,64] symmetric rank-k (upper CTAs)
// Output: [recon | z_mean | z_log_std]
//
// Compensation: a = ah + al (bf16 hi + bf16 residual);
//   C = Ah*Bl + Al*Bh + Ah*Bh   (Al*Bl ~2^-18 dropped) -> ~1e-5 per GEMM.
// R13 changes: cp.async (cg, 16B) into an fp32 smem staging buffer, issued one
// tile ahead right after the barrier so gmem latency hides under the mma
// phase. Each thread stages exactly the chunks it converts (own-chunk
// readback -> wait_group is sufficient). Convert phase now waits on LDS (29
// cyc) instead of LDG (~600 cyc). Math identical to R12.
// ---------------------------------------------------------------------------

#define NN   8192
#define DIN  512
#define DHID 256
#define DZ   64
#define DCAT 128

// ---- scratch (allocation-free) ----
#define SZ_PART     (16*NN*DCAT)
#define OFF_SUPPORT 0
#define OFF_HIDDEN  (OFF_SUPPORT + NN*DHID)
#define OFF_PART    (OFF_HIDDEN  + NN*DHID)
#define OFF_S       (OFF_PART    + SZ_PART)
#define OFF_WCAT    (OFF_S       + NN*DCAT)
#define SZ_TOTAL    (OFF_WCAT    + DHID*DCAT)

__device__ __align__(16) float g_scratch[SZ_TOTAL];

// ---------------------------------------------------------------------------
// helpers
// ---------------------------------------------------------------------------
__device__ __forceinline__ uint32_t smem_u32(const void* p) {
    uint32_t a;
    asm("{ .reg .u64 t; cvta.to.shared.u64 t, %1; cvt.u32.u64 %0, t; }"
        : "=r"(a) : "l"(p));
    return a;
}

__device__ __forceinline__ uint32_t pack_bf2(float lo, float hi) {
    uint32_t r;
    asm("cvt.rn.bf16x2.f32 %0, %1, %2;" : "=r"(r) : "f"(hi), "f"(lo));
    return r;
}

__device__ __forceinline__ void ldm_x4(uint32_t* r, uint32_t addr) {
    asm volatile("ldmatrix.sync.aligned.m8n8.x4.shared.b16 {%0,%1,%2,%3}, [%4];"
                 : "=r"(r[0]), "=r"(r[1]), "=r"(r[2]), "=r"(r[3]) : "r"(addr));
}

__device__ __forceinline__ void ldm_x4_t(uint32_t* r, uint32_t addr) {
    asm volatile("ldmatrix.sync.aligned.m8n8.x4.trans.shared.b16 {%0,%1,%2,%3}, [%4];"
                 : "=r"(r[0]), "=r"(r[1]), "=r"(r[2]), "=r"(r[3]) : "r"(addr));
}

__device__ __forceinline__ void mma_bf16(float* c, const uint32_t* a, const uint32_t* b) {
    asm volatile(
        "mma.sync.aligned.m16n8k16.row.col.f32.bf16.bf16.f32 "
        "{%0,%1,%2,%3}, {%4,%5,%6,%7}, {%8,%9}, {%0,%1,%2,%3};"
        : "+f"(c[0]), "+f"(c[1]), "+f"(c[2]), "+f"(c[3])
        : "r"(a[0]), "r"(a[1]), "r"(a[2]), "r"(a[3]), "r"(b[0]), "r"(b[1]));
}

__device__ __forceinline__ void split_pack(float4 v, uint2& hp, uint2& lp) {
    hp.x = pack_bf2(v.x, v.y);
    hp.y = pack_bf2(v.z, v.w);
    float h0 = __uint_as_float(hp.x << 16);
    float h1 = __uint_as_float(hp.x & 0xffff0000u);
    float h2 = __uint_as_float(hp.y << 16);
    float h3 = __uint_as_float(hp.y & 0xffff0000u);
    lp.x = pack_bf2(v.x - h0, v.y - h1);
    lp.y = pack_bf2(v.z - h2, v.w - h3);
}

__device__ __forceinline__ void cp_async16(uint32_t dst, const void* src) {
    asm volatile("cp.async.cg.shared.global [%0], [%1], 16;"
                 :: "r"(dst), "l"(src) : "memory");
}
#define CP_COMMIT() asm volatile("cp.async.commit_group;" ::: "memory")
#define CP_WAIT0()  asm volatile("cp.async.wait_group 0;" ::: "memory")

__device__ __forceinline__ float4 lds128(uint32_t a) {
    float4 v;
    asm volatile("ld.shared.v4.f32 {%0,%1,%2,%3}, [%4];"
                 : "=f"(v.x), "=f"(v.y), "=f"(v.z), "=f"(v.w) : "r"(a));
    return v;
}

// ---------------------------------------------------------------------------
// smem layouts
// ---------------------------------------------------------------------------
#define PITCH   80                  // A bf16 tiles: [m][64B of k], 80B pitch
#define SEGSZ   (128 * PITCH)       // 10240
#define PITCHB  272                 // B bf16 tiles: [k][256B of n], 272B pitch
#define SEGB    (32 * PITCHB)       // 8704

// nmajor bf16 stage layout
#define N_AH    0
#define N_AL    (1 * SEGSZ)
#define N_BH    (2 * SEGSZ)
#define N_BL    (2 * SEGSZ + SEGB)
#define N_STAGE (2 * SEGSZ + 2 * SEGB)   // 37888
// fp32 cp.async staging (single buffer): A 128x128B, B 32x512B
#define STG_A   (2 * N_STAGE)            // 75776
#define STG_B   (STG_A + 16384)          // 92160
#define N_SMEM  (STG_B + 16384)          // 108544

// kmajor (syrk) stage layout — unchanged
#define SEG_AH  0
#define SEG_AL  (1 * SEGSZ)
#define SEG_BL  (2 * SEGSZ)
#define SEG_BH  (3 * SEGSZ)
#define GSTAGE  (4 * SEGSZ)              // 40960
#define K_SMEM  (2 * GSTAGE)             // 81920

// ---------------------------------------------------------------------------
// bf16x3 GEMM, B in natural [K,N] row-major: C = A[M,K] @ B[K,N].
// BM=BN=128, BK=32. 256 threads, warps 4(m) x 2(n), warp tile 32x64.
// cp.async fp32 staging issued one tile ahead; 2 bf16 stages; ONE barrier
// per k-tile; occupancy 2. grid=(N/128, M/128, K/kChunk).
// ---------------------------------------------------------------------------
__global__ void __launch_bounds__(256, 2)
bf16x3_gemm_bn(const float* __restrict__ A, const float* __restrict__ B,
               float* __restrict__ C, int M, int N, int K, int ldB, int kChunk)
{
    extern __shared__ __align__(16) char sm[];
    const uint32_t smb = smem_u32(sm);

    const int tid = threadIdx.x;
    const int wid = tid >> 5;
    const int lane = tid & 31;
    const int warp_m = wid & 3;
    const int warp_n = wid >> 2;

    const int m0 = blockIdx.y * 128;
    const int n0 = blockIdx.x * 128;
    const int kBeg = blockIdx.z * kChunk;
    const int nkt = kChunk >> 5;
    float* Cout = C + (size_t)blockIdx.z * (size_t)M * (size_t)N;

    float acc[2][8][4];
#pragma unroll
    for (int mt = 0; mt < 2; mt++)
#pragma unroll
        for (int nf = 0; nf < 8; nf++)
#pragma unroll
            for (int e = 0; e < 4; e++) acc[mt][nf][e] = 0.f;

    // A loader: thread -> (row = lr + 32i, k-float4 = c4)
    const int lr = tid >> 3;
    const int c4 = tid & 7;
    const float* Ab = A + (size_t)(m0 + lr) * (size_t)K + c4 * 4;
    const uint32_t stA = (uint32_t)(lr * PITCH + c4 * 8);
    const uint32_t sgA = smb + STG_A + (uint32_t)(lr * 128 + c4 * 16);

    // B loader: thread -> (k-row = kq, n-chunk = ncb + 8i)
    const int kq = tid >> 3;
    const int ncb = tid & 7;
    const float* Bb = B + (size_t)kq * (size_t)ldB + n0 + ncb * 4;
    const uint32_t stB = (uint32_t)(kq * PITCHB + ncb * 8);
    const uint32_t sgB = smb + STG_B + (uint32_t)(kq * 512 + ncb * 16);

    // ldmatrix fragment addresses
    const uint32_t a_row = (uint32_t)(warp_m * 32 + (lane & 15));
    const uint32_t a_off = a_row * PITCH + ((uint32_t)(lane >> 4) << 4);
    const uint32_t b_row = (uint32_t)((lane & 7) + ((lane >> 3) & 1) * 8);
    const uint32_t b_off = b_row * PITCHB + (uint32_t)warp_n * 128u
                         + (((uint32_t)lane >> 4) << 4);

    // prologue: stage tile 0
    {
        const int k0 = kBeg;
#pragma unroll
        for (int i = 0; i < 4; i++) {
            cp_async16(sgA + (uint32_t)(i * 32 * 128),
                       Ab + (size_t)(i * 32) * (size_t)K + k0);
            cp_async16(sgB + (uint32_t)(i * 128),
                       Bb + (size_t)k0 * (size_t)ldB + i * 32);
        }
        CP_COMMIT();
    }

    for (int kt = 0; kt < nkt; kt++) {
        const uint32_t stg = (uint32_t)(kt & 1) * N_STAGE;
        char* sp = sm + stg;

        // ---- staging ready (own chunks) -> convert -> bf16 tiles ----
        CP_WAIT0();
#pragma unroll
        for (int i = 0; i < 4; i++) {
            float4 va = lds128(sgA + (uint32_t)(i * 32 * 128));
            uint2 hp, lp;
            split_pack(va, hp, lp);
            const uint32_t offA = stA + (uint32_t)(i * 32 * PITCH);
            *(uint2*)(sp + N_AH + offA) = hp;
            *(uint2*)(sp + N_AL + offA) = lp;
            float4 vb = lds128(sgB + (uint32_t)(i * 128));
            split_pack(vb, hp, lp);
            const uint32_t offB = stB + (uint32_t)(i * 64);
            *(uint2*)(sp + N_BH + offB) = hp;
            *(uint2*)(sp + N_BL + offB) = lp;
        }
        __syncthreads();

        // ---- issue next tile's cp.async (hides under mma phase) ----
        if (kt + 1 < nkt) {
            const int k1 = kBeg + ((kt + 1) << 5);
#pragma unroll
            for (int i = 0; i < 4; i++) {
                cp_async16(sgA + (uint32_t)(i * 32 * 128),
                           Ab + (size_t)(i * 32) * (size_t)K + k1);
                cp_async16(sgB + (uint32_t)(i * 128),
                           Bb + (size_t)k1 * (size_t)ldB + i * 32);
            }
        }
        CP_COMMIT();

        // ---- compute: 2 k16 steps x 3 compensation passes ----
        const uint32_t sa = smb + stg + a_off;
        const uint32_t sb = smb + stg + b_off;
#pragma unroll
        for (int kk = 0; kk < 2; kk++) {
            const uint32_t kbA = (uint32_t)(kk * 32);
            const uint32_t kbB = (uint32_t)(kk * 16 * PITCHB);
            uint32_t Ah[2][4], Al[2][4];
#pragma unroll
            for (int mt = 0; mt < 2; mt++) {
                const uint32_t base = sa + (uint32_t)(mt * 16 * PITCH) + kbA;
                ldm_x4(Ah[mt], base + N_AH);
                ldm_x4(Al[mt], base + N_AL);
            }
            uint32_t Bf[8][2];
#pragma unroll
            for (int nf2 = 0; nf2 < 4; nf2++) {
                uint32_t t[4];
                ldm_x4_t(t, sb + N_BL + (uint32_t)(nf2 * 32) + kbB);
                Bf[2 * nf2][0] = t[0]; Bf[2 * nf2][1] = t[1];
                Bf[2 * nf2 + 1][0] = t[2]; Bf[2 * nf2 + 1][1] = t[3];
            }
#pragma unroll
            for (int mt = 0; mt < 2; mt++)
#pragma unroll
                for (int nf = 0; nf < 8; nf++)
                    mma_bf16(acc[mt][nf], Ah[mt], Bf[nf]);
#pragma unroll
            for (int nf2 = 0; nf2 < 4; nf2++) {
                uint32_t t[4];
                ldm_x4_t(t, sb + N_BH + (uint32_t)(nf2 * 32) + kbB);
                Bf[2 * nf2][0] = t[0]; Bf[2 * nf2][1] = t[1];
                Bf[2 * nf2 + 1][0] = t[2]; Bf[2 * nf2 + 1][1] = t[3];
            }
#pragma unroll
            for (int mt = 0; mt < 2; mt++)
#pragma unroll
                for (int nf = 0; nf < 8; nf++) {
                    mma_bf16(acc[mt][nf], Al[mt], Bf[nf]);
                    mma_bf16(acc[mt][nf], Ah[mt], Bf[nf]);
                }
        }
    }

    const int erow = m0 + warp_m * 32 + (lane >> 2);
    const int ecol = n0 + warp_n * 64 + 2 * (lane & 3);
#pragma unroll
    for (int mt = 0; mt < 2; mt++) {
#pragma unroll
        for (int nf = 0; nf < 8; nf++) {
            float* p0 = Cout + (size_t)(erow + mt * 16) * (size_t)N + ecol + nf * 8;
            float* p1 = p0 + (size_t)8 * (size_t)N;
            *(float2*)p0 = make_float2(acc[mt][nf][0], acc[mt][nf][1]);
            *(float2*)p1 = make_float2(acc[mt][nf][2], acc[mt][nf][3]);
        }
    }
}

// ---------------------------------------------------------------------------
// Symmetric rank-k (K-major path, unchanged): C = Z @ Z^T, upper CTAs only.
// ---------------------------------------------------------------------------
__global__ void __launch_bounds__(256, 2)
bf16x3_syrk(const float* __restrict__ Z, float* __restrict__ C)
{
    const int bi = blockIdx.y, bj = blockIdx.x;
    if (bj < bi) return;

    extern __shared__ __align__(16) char sm[];
    const uint32_t smb = smem_u32(sm);

    const int tid = threadIdx.x;
    const int wid = tid >> 5;
    const int lane = tid & 31;
    const int warp_m = wid & 3;
    const int warp_n = wid >> 2;

    const int m0 = bi * 128;
    const int n0 = bj * 128;
    const int K = DZ;

    float acc[2][8][4];
#pragma unroll
    for (int mt = 0; mt < 2; mt++)
#pragma unroll
        for (int nf = 0; nf < 8; nf++)
#pragma unroll
            for (int e = 0; e < 4; e++) acc[mt][nf][e] = 0.f;

    const int lr = tid >> 3;
    const int c4 = tid & 7;
    const float* Ab = Z + (size_t)(m0 + lr) * (size_t)K + c4 * 4;
    const float* Bb = Z + (size_t)(n0 + lr) * (size_t)K + c4 * 4;
    const uint32_t stoff = (uint32_t)(lr * PITCH + c4 * 8);

    const uint32_t a_row = (uint32_t)(warp_m * 32 + (lane & 15));
    const uint32_t a_off = a_row * PITCH + ((uint32_t)(lane >> 4) << 4);
    const uint32_t b_row = (uint32_t)(warp_n * 64 + (lane & 7) + ((lane >> 4) << 3));
    const uint32_t b_off = b_row * PITCH + (((uint32_t)(lane >> 3) & 1) << 4);

    for (int kt = 0; kt < 2; kt++) {
        const uint32_t stg = (uint32_t)(kt & 1) * GSTAGE;
        char* sp = sm + stg;
        const int k0 = kt << 5;
#pragma unroll
        for (int i = 0; i < 4; i++) {
            const uint32_t off = stoff + (uint32_t)(i * 32 * PITCH);
            float4 va = *(const float4*)(Ab + (size_t)(i * 32) * (size_t)K + k0);
            float4 vb = *(const float4*)(Bb + (size_t)(i * 32) * (size_t)K + k0);
            uint2 hp, lp;
            split_pack(va, hp, lp);
            *(uint2*)(sp + SEG_AH + off) = hp;
            *(uint2*)(sp + SEG_AL + off) = lp;
            split_pack(vb, hp, lp);
            *(uint2*)(sp + SEG_BH + off) = hp;
            *(uint2*)(sp + SEG_BL + off) = lp;
        }
        __syncthreads();
        const uint32_t sa = smb + stg + a_off;
        const uint32_t sb = smb + stg + b_off;
#pragma unroll
        for (int kk = 0; kk < 2; kk++) {
            const uint32_t kb = (uint32_t)(kk * 32);
            uint32_t Ah[2][4], Al[2][4];
#pragma unroll
            for (int mt = 0; mt < 2; mt++) {
                const uint32_t base = sa + (uint32_t)(mt * 16 * PITCH) + kb;
                ldm_x4(Ah[mt], base + SEG_AH);
                ldm_x4(Al[mt], base + SEG_AL);
            }
            uint32_t Bf[8][2];
#pragma unroll
            for (int nf2 = 0; nf2 < 4; nf2++) {
                uint32_t t[4];
                ldm_x4(t, sb + SEG_BL + (uint32_t)(nf2 * 16 * PITCH) + kb);
                Bf[2 * nf2][0] = t[0]; Bf[2 * nf2][1] = t[1];
                Bf[2 * nf2 + 1][0] = t[2]; Bf[2 * nf2 + 1][1] = t[3];
            }
#pragma unroll
            for (int mt = 0; mt < 2; mt++)
#pragma unroll
                for (int nf = 0; nf < 8; nf++)
                    mma_bf16(acc[mt][nf], Ah[mt], Bf[nf]);
#pragma unroll
            for (int nf2 = 0; nf2 < 4; nf2++) {
                uint32_t t[4];
                ldm_x4(t, sb + SEG_BH + (uint32_t)(nf2 * 16 * PITCH) + kb);
                Bf[2 * nf2][0] = t[0]; Bf[2 * nf2][1] = t[1];
                Bf[2 * nf2 + 1][0] = t[2]; Bf[2 * nf2 + 1][1] = t[3];
            }
#pragma unroll
            for (int mt = 0; mt < 2; mt++)
#pragma unroll
                for (int nf = 0; nf < 8; nf++) {
                    mma_bf16(acc[mt][nf], Al[mt], Bf[nf]);
                    mma_bf16(acc[mt][nf], Ah[mt], Bf[nf]);
                }
        }
    }

    const int erow0 = warp_m * 32 + (lane >> 2);
    const int ecol0 = warp_n * 64 + 2 * (lane & 3);
#pragma unroll
    for (int mt = 0; mt < 2; mt++) {
#pragma unroll
        for (int nf = 0; nf < 8; nf++) {
            float* p0 = C + (size_t)(m0 + erow0 + mt * 16) * (size_t)NN
                          + n0 + ecol0 + nf * 8;
            float* p1 = p0 + (size_t)8 * (size_t)NN;
            *(float2*)p0 = make_float2(acc[mt][nf][0], acc[mt][nf][1]);
            *(float2*)p1 = make_float2(acc[mt][nf][2], acc[mt][nf][3]);
        }
    }

    if (bi != bj) {
        __syncthreads();
        float* smT = (float*)sm;               // [128][132]
#pragma unroll
        for (int mt = 0; mt < 2; mt++)
#pragma unroll
            for (int nf = 0; nf < 8; nf++) {
                const int rr = erow0 + mt * 16;
                const int cc = ecol0 + nf * 8;
                smT[(cc + 0) * 132 + rr]     = acc[mt][nf][0];
                smT[(cc + 1) * 132 + rr]     = acc[mt][nf][1];
                smT[(cc + 0) * 132 + rr + 8] = acc[mt][nf][2];
                smT[(cc + 1) * 132 + rr + 8] = acc[mt][nf][3];
            }
        __syncthreads();
        const int r2 = tid >> 1;
        const int half = (tid & 1) * 64;
        float* dst = C + (size_t)(n0 + r2) * (size_t)NN + m0 + half;
        const float* src = smT + r2 * 132 + half;
#pragma unroll
        for (int j = 0; j < 16; j++)
            *(float4*)(dst + j * 4) = *(const float4*)(src + j * 4);
    }
}

// ---------------------------------------------------------------------------
// helpers: pack, reducers
// ---------------------------------------------------------------------------
__global__ void pack_wcat(const float* __restrict__ Wm, const float* __restrict__ Wl,
                          float* __restrict__ Wcat) {
    int i = blockIdx.x * blockDim.x + threadIdx.x;
    if (i >= DHID * DCAT) return;
    int k = i >> 7, c = i & 127;
    Wcat[i] = (c < DZ) ? Wm[k * DZ + c] : Wl[k * DZ + (c - DZ)];
}

template<int S, bool RELU>
__global__ void reduceN(const float* __restrict__ p, size_t stride,
                        float* __restrict__ out, int n4) {
    int base = blockIdx.x * (blockDim.x * 4) + threadIdx.x;
#pragma unroll
    for (int j = 0; j < 4; j++) {
        int i = base + j * 256;
        if (i >= n4) return;
        float4 r = ((const float4*)p)[i];
#pragma unroll
        for (int s = 1; s < S; s++) {
            float4 v = ((const float4*)(p + (size_t)s * stride))[i];
            r.x += v.x; r.y += v.y; r.z += v.z; r.w += v.w;
        }
        if (RELU) {
            r.x = fmaxf(r.x, 0.f); r.y = fmaxf(r.y, 0.f);
            r.z = fmaxf(r.z, 0.f); r.w = fmaxf(r.w, 0.f);
        }
        ((float4*)out)[i] = r;
    }
}

__global__ void reduce16_split(const float* __restrict__ p, size_t stride,
                               float* __restrict__ zm, float* __restrict__ zl) {
    int base = blockIdx.x * (blockDim.x * 4) + threadIdx.x;
#pragma unroll
    for (int j = 0; j < 4; j++) {
        int i = base + j * 256;
        if (i >= NN * DCAT / 4) return;
        int row = i >> 5, c4 = i & 31;
        float4 r = ((const float4*)p)[i];
#pragma unroll
        for (int s = 1; s < 16; s++) {
            float4 v = ((const float4*)(p + (size_t)s * stride))[i];
            r.x += v.x; r.y += v.y; r.z += v.z; r.w += v.w;
        }
        if (c4 < 16) ((float4*)zm)[(size_t)row * 16 + c4] = r;
        else         ((float4*)zl)[(size_t)row * 16 + (c4 - 16)] = r;
    }
}

// ---------------------------------------------------------------------------
extern "C" void kernel_launch(void* const* d_in, const int* in_sizes, int n_in,
                              void* d_out, int out_size) {
    const float* x = nullptr;
    const float* adj = nullptr;
    const float* Wh = nullptr;
    const float* Wsmall[2] = {nullptr, nullptr};
    int nsmall = 0;
    for (int i = 0; i < n_in; i++) {
        const float* p = (const float*)d_in[i];
        switch (in_sizes[i]) {
            case NN * DIN:   x = p; break;
            case NN * NN:    adj = p; break;
            case DIN * DHID: Wh = p; break;
            case DHID * DZ:  if (nsmall < 2) Wsmall[nsmall++] = p; break;
            default: break;
        }
    }
    const float* Wm = Wsmall[0];
    const float* Wl = Wsmall[1];

    float* out = (float*)d_out;
    float* recon = out;
    float* zm = out + (size_t)NN * (size_t)NN;
    float* zl = zm + (size_t)NN * (size_t)DZ;

    float* ws = nullptr;
    cudaGetSymbolAddress((void**)&ws, g_scratch);
    float* support = ws + OFF_SUPPORT;
    float* hidden  = ws + OFF_HIDDEN;
    float* part    = ws + OFF_PART;
    float* sbuf    = ws + OFF_S;
    float* wcat    = ws + OFF_WCAT;

    cudaFuncSetAttribute(bf16x3_gemm_bn, cudaFuncAttributeMaxDynamicSharedMemorySize,
                         N_SMEM);
    cudaFuncSetAttribute(bf16x3_syrk, cudaFuncAttributeMaxDynamicSharedMemorySize,
                         K_SMEM);

    pack_wcat<<<(DHID * DCAT + 255) / 256, 256>>>(Wm, Wl, wcat);

    // support = x @ Wh, split-K 2
    bf16x3_gemm_bn<<<dim3(2, 64, 2), 256, N_SMEM>>>(x, Wh, part, NN, DHID, DIN,
                                                    DHID, DIN / 2);
    reduceN<2, false><<<(NN * DHID / 4 + 1023) / 1024, 256>>>(part, (size_t)NN * DHID,
                                                              support, NN * DHID / 4);

    // hidden = relu(adj @ support), split-K 8
    bf16x3_gemm_bn<<<dim3(2, 64, 8), 256, N_SMEM>>>(adj, support, part, NN, DHID, NN,
                                                    DHID, NN / 8);
    reduceN<8, true><<<(NN * DHID / 4 + 1023) / 1024, 256>>>(part, (size_t)NN * DHID,
                                                             hidden, NN * DHID / 4);

    // s = hidden @ [Wm|Wl], split-K 4
    bf16x3_gemm_bn<<<dim3(1, 64, 4), 256, N_SMEM>>>(hidden, wcat, part, NN, DCAT, DHID,
                                                    DCAT, DHID / 4);
    reduceN<4, false><<<(NN * DCAT / 4 + 1023) / 1024, 256>>>(part, (size_t)NN * DCAT,
                                                              sbuf, NN * DCAT / 4);

    // zcat = adj @ s, split-K 16 -> z_mean, z_log_std
    bf16x3_gemm_bn<<<dim3(1, 64, 16), 256, N_SMEM>>>(adj, sbuf, part, NN, DCAT, NN,
                                                     DCAT, NN / 16);
    reduce16_split<<<(NN * DCAT / 4 + 1023) / 1024, 256>>>(part, (size_t)NN * DCAT,
                                                           zm, zl);

    // recon = z_mean @ z_mean^T (symmetric)
    bf16x3_syrk<<<dim3(64, 64), 256, K_SMEM>>>(zm, recon);
}